// round 2
// baseline (speedup 1.0000x reference)
#include <cuda_runtime.h>
#include <math.h>

#define E_    2048
#define HQ_   16
#define HK_   4
#define D_    128
#define KVE_  512
#define B_    2
#define N_    2048
#define MR_   (B_ * N_)   // 4096 rows

// ---------------- scratch (no allocations allowed) ----------------
__device__ float g_Q[(size_t)MR_ * E_];    // 32 MB  (pre-scaled q, (b n, hq d))
__device__ float g_K[(size_t)MR_ * KVE_];  //  8 MB  ((b n, hk d))
__device__ float g_V[(size_t)MR_ * KVE_];  //  8 MB
__device__ float g_A[(size_t)MR_ * E_];    // 32 MB  (attention out, (b n, hq d))

// =================================================================
// NT GEMM:  C[m,n] = (sum_k A[m,k] * W[n,k] + bias[n]) * scale
// A: M x K row-major, W: N x K row-major. Tiles 128x128x16, 8x8/thread.
// =================================================================
__global__ void __launch_bounds__(256, 2) gemm_nt_bias(
    const float* __restrict__ A, const float* __restrict__ W,
    const float* __restrict__ bias, float* __restrict__ C,
    int M, int Nn, int K, float scale)
{
    __shared__ float As[16][128];
    __shared__ float Ws[16][128];

    const int tid = threadIdx.x;
    const int m0 = blockIdx.y * 128;
    const int n0 = blockIdx.x * 128;
    const int ty = tid >> 4;          // 0..15
    const int tx = tid & 15;          // 0..15

    const int lrow = tid >> 1;        // 0..127
    const int lk   = (tid & 1) << 3;  // 0 or 8

    const float* Ag = A + (size_t)(m0 + lrow) * K + lk;
    const float* Wg = W + (size_t)(n0 + lrow) * K + lk;

    float acc[8][8];
#pragma unroll
    for (int i = 0; i < 8; i++)
#pragma unroll
        for (int j = 0; j < 8; j++) acc[i][j] = 0.f;

    for (int kt = 0; kt < K; kt += 16) {
        float4 a0 = *(const float4*)(Ag + kt);
        float4 a1 = *(const float4*)(Ag + kt + 4);
        float4 w0 = *(const float4*)(Wg + kt);
        float4 w1 = *(const float4*)(Wg + kt + 4);
        As[lk + 0][lrow] = a0.x; As[lk + 1][lrow] = a0.y;
        As[lk + 2][lrow] = a0.z; As[lk + 3][lrow] = a0.w;
        As[lk + 4][lrow] = a1.x; As[lk + 5][lrow] = a1.y;
        As[lk + 6][lrow] = a1.z; As[lk + 7][lrow] = a1.w;
        Ws[lk + 0][lrow] = w0.x; Ws[lk + 1][lrow] = w0.y;
        Ws[lk + 2][lrow] = w0.z; Ws[lk + 3][lrow] = w0.w;
        Ws[lk + 4][lrow] = w1.x; Ws[lk + 5][lrow] = w1.y;
        Ws[lk + 6][lrow] = w1.z; Ws[lk + 7][lrow] = w1.w;
        __syncthreads();

#pragma unroll
        for (int k = 0; k < 16; k++) {
            float af[8], wf[8];
            *(float4*)&af[0] = *(const float4*)&As[k][ty * 8];
            *(float4*)&af[4] = *(const float4*)&As[k][ty * 8 + 4];
            *(float4*)&wf[0] = *(const float4*)&Ws[k][tx * 8];
            *(float4*)&wf[4] = *(const float4*)&Ws[k][tx * 8 + 4];
#pragma unroll
            for (int i = 0; i < 8; i++)
#pragma unroll
                for (int j = 0; j < 8; j++)
                    acc[i][j] = fmaf(af[i], wf[j], acc[i][j]);
        }
        __syncthreads();
    }

    float4 b0 = *(const float4*)(bias + n0 + tx * 8);
    float4 b1 = *(const float4*)(bias + n0 + tx * 8 + 4);
#pragma unroll
    for (int i = 0; i < 8; i++) {
        size_t row = (size_t)(m0 + ty * 8 + i);
        float4 v0, v1;
        v0.x = (acc[i][0] + b0.x) * scale;
        v0.y = (acc[i][1] + b0.y) * scale;
        v0.z = (acc[i][2] + b0.z) * scale;
        v0.w = (acc[i][3] + b0.w) * scale;
        v1.x = (acc[i][4] + b1.x) * scale;
        v1.y = (acc[i][5] + b1.y) * scale;
        v1.z = (acc[i][6] + b1.z) * scale;
        v1.w = (acc[i][7] + b1.w) * scale;
        *(float4*)(C + row * Nn + n0 + tx * 8)     = v0;
        *(float4*)(C + row * Nn + n0 + tx * 8 + 4) = v1;
    }
}

// =================================================================
// Flash attention (fp32, online softmax).
// Q pre-scaled by 1/sqrt(D). Block: 64 q-rows x one (b, hq).
// Smem: Qs/Ks stored d-major with stride 68 ([d][r], conflict-free
// float4 fragment reads), Vs row-major, Ps transposed [s][r].
// =================================================================
#define AQB 64
#define AKB 64
#define QK_STRIDE 68   // 64 + 4 pad, keeps float4 alignment
#define ATTN_SMEM_FLOATS (128*QK_STRIDE /*Qs*/ + 128*QK_STRIDE /*Ks*/ + 64*128 /*Vs*/ + 64*QK_STRIDE /*Ps*/)

__global__ void __launch_bounds__(256, 1) attn_kernel(
    const float* __restrict__ Qg, const float* __restrict__ Kg,
    const float* __restrict__ Vg, float* __restrict__ Og,
    const int* __restrict__ causal_p)
{
    extern __shared__ float sm[];
    float* Qs = sm;                          // [128][68]  (d-major)
    float* Ks = Qs + 128 * QK_STRIDE;        // [128][68]
    float* Vs = Ks + 128 * QK_STRIDE;        // [64][128]
    float* Ps = Vs + 64 * 128;               // [64][68]   (P transposed: [s][r])

    const int tid = threadIdx.x;
    const int ty = tid >> 4;      // 0..15
    const int tx = tid & 15;      // 0..15
    const int qb = blockIdx.x;    // 0..31
    const int bh = blockIdx.y;    // 0..31
    const int b  = bh >> 4;
    const int hq = bh & 15;
    const int hk = hq >> 2;       // G = 4

    const int r0 = ty * 4;        // S rows of this thread
    const int c0 = tx * 4;        // S cols
    const int v0 = tx * 8;        // O cols
    const bool causal = (causal_p[0] != 0);

    // ---- load Q tile (64 x 128) once, store d-major ----
    // 64 rows * 32 float4/row = 2048 float4 slots, 256 threads -> 8 iters
    {
        const float* src = Qg + ((size_t)(b * N_ + qb * AQB)) * E_ + hq * D_;
#pragma unroll
        for (int it = 0; it < 8; it++) {
            int fi = tid + it * 256;     // 0..2047
            int r  = fi >> 5;            // 0..63
            int dq = fi & 31;            // 0..31
            float4 v = *(const float4*)(src + (size_t)r * E_ + dq * 4);
            int d0 = dq * 4;
            float* q = Qs + d0 * QK_STRIDE + r;
            q[0 * QK_STRIDE] = v.x; q[1 * QK_STRIDE] = v.y;
            q[2 * QK_STRIDE] = v.z; q[3 * QK_STRIDE] = v.w;
        }
    }

    float m_i[4], l_i[4], o[4][8];
#pragma unroll
    for (int i = 0; i < 4; i++) { m_i[i] = -1e30f; l_i[i] = 0.f; }
#pragma unroll
    for (int i = 0; i < 4; i++)
#pragma unroll
        for (int j = 0; j < 8; j++) o[i][j] = 0.f;

    const int ktend = causal ? (qb + 1) : (N_ / AKB);

    for (int kt = 0; kt < ktend; kt++) {
        __syncthreads();   // prior PV readers done before overwriting Ks/Vs

        // ---- load K (d-major) and V (row-major) tiles ----
        {
            const float* ksrc = Kg + ((size_t)(b * N_ + kt * AKB)) * KVE_ + hk * D_;
            const float* vsrc = Vg + ((size_t)(b * N_ + kt * AKB)) * KVE_ + hk * D_;
#pragma unroll
            for (int it = 0; it < 8; it++) {
                int fi = tid + it * 256;
                int r  = fi >> 5;
                int dq = fi & 31;
                int d0 = dq * 4;
                float4 kv = *(const float4*)(ksrc + (size_t)r * KVE_ + dq * 4);
                float* p = Ks + d0 * QK_STRIDE + r;
                p[0 * QK_STRIDE] = kv.x; p[1 * QK_STRIDE] = kv.y;
                p[2 * QK_STRIDE] = kv.z; p[3 * QK_STRIDE] = kv.w;
                float4 vv = *(const float4*)(vsrc + (size_t)r * KVE_ + dq * 4);
                *(float4*)&Vs[r * 128 + d0] = vv;
            }
        }
        __syncthreads();

        // ---- S = Q K^T (4x4 per thread over d=128) ----
        float s[4][4];
#pragma unroll
        for (int i = 0; i < 4; i++)
#pragma unroll
            for (int j = 0; j < 4; j++) s[i][j] = 0.f;

#pragma unroll 16
        for (int dk = 0; dk < 128; dk++) {
            float qr[4], kr[4];
            *(float4*)qr = *(const float4*)(Qs + dk * QK_STRIDE + r0);
            *(float4*)kr = *(const float4*)(Ks + dk * QK_STRIDE + c0);
#pragma unroll
            for (int i = 0; i < 4; i++)
#pragma unroll
                for (int j = 0; j < 4; j++)
                    s[i][j] = fmaf(qr[i], kr[j], s[i][j]);
        }

        // ---- causal mask (only the diagonal tile needs it) ----
        if (causal && kt == qb) {
            const int qrow = qb * AQB + r0;
            const int kcol = kt * AKB + c0;
#pragma unroll
            for (int i = 0; i < 4; i++)
#pragma unroll
                for (int j = 0; j < 4; j++)
                    if (kcol + j > qrow + i) s[i][j] = -1e30f;
        }

        // ---- online softmax (row stats across the 16-lane tx group) ----
#pragma unroll
        for (int i = 0; i < 4; i++) {
            float rm = fmaxf(fmaxf(s[i][0], s[i][1]), fmaxf(s[i][2], s[i][3]));
            rm = fmaxf(rm, __shfl_xor_sync(0xffffffffu, rm, 1));
            rm = fmaxf(rm, __shfl_xor_sync(0xffffffffu, rm, 2));
            rm = fmaxf(rm, __shfl_xor_sync(0xffffffffu, rm, 4));
            rm = fmaxf(rm, __shfl_xor_sync(0xffffffffu, rm, 8));
            float mnew  = fmaxf(m_i[i], rm);
            float alpha = __expf(m_i[i] - mnew);
            m_i[i] = mnew;
            float rs = 0.f;
#pragma unroll
            for (int j = 0; j < 4; j++) {
                float p = __expf(s[i][j] - mnew);
                s[i][j] = p;
                rs += p;
            }
            rs += __shfl_xor_sync(0xffffffffu, rs, 1);
            rs += __shfl_xor_sync(0xffffffffu, rs, 2);
            rs += __shfl_xor_sync(0xffffffffu, rs, 4);
            rs += __shfl_xor_sync(0xffffffffu, rs, 8);
            l_i[i] = l_i[i] * alpha + rs;
#pragma unroll
            for (int j = 0; j < 8; j++) o[i][j] *= alpha;
            // write P transposed: Ps[s][r]
#pragma unroll
            for (int j = 0; j < 4; j++)
                Ps[(c0 + j) * QK_STRIDE + (r0 + i)] = s[i][j];
        }
        __syncthreads();

        // ---- O += P V  (4x8 per thread over s=64) ----
#pragma unroll 8
        for (int ss = 0; ss < 64; ss++) {
            float pf[4], vf[8];
            *(float4*)pf    = *(const float4*)(Ps + ss * QK_STRIDE + r0);
            *(float4*)&vf[0] = *(const float4*)(Vs + ss * 128 + v0);
            *(float4*)&vf[4] = *(const float4*)(Vs + ss * 128 + v0 + 4);
#pragma unroll
            for (int i = 0; i < 4; i++)
#pragma unroll
                for (int j = 0; j < 8; j++)
                    o[i][j] = fmaf(pf[i], vf[j], o[i][j]);
        }
    }

    // ---- normalize + write out in (b n, hq d) layout ----
#pragma unroll
    for (int i = 0; i < 4; i++) {
        float inv = 1.f / l_i[i];
        float* dst = Og + ((size_t)(b * N_ + qb * AQB + r0 + i)) * E_ + hq * D_ + v0;
        float4 t0, t1;
        t0.x = o[i][0] * inv; t0.y = o[i][1] * inv;
        t0.z = o[i][2] * inv; t0.w = o[i][3] * inv;
        t1.x = o[i][4] * inv; t1.y = o[i][5] * inv;
        t1.z = o[i][6] * inv; t1.w = o[i][7] * inv;
        *(float4*)(dst)     = t0;
        *(float4*)(dst + 4) = t1;
    }
}

// =================================================================
extern "C" void kernel_launch(void* const* d_in, const int* in_sizes, int n_in,
                              void* d_out, int out_size)
{
    const float* query = (const float*)d_in[0];
    const float* key   = (const float*)d_in[1];
    const float* value = (const float*)d_in[2];
    const float* Wq = (const float*)d_in[3];
    const float* bq = (const float*)d_in[4];
    const float* Wk = (const float*)d_in[5];
    const float* bk = (const float*)d_in[6];
    const float* Wv = (const float*)d_in[7];
    const float* bv = (const float*)d_in[8];
    const float* Wo = (const float*)d_in[9];
    const float* bo = (const float*)d_in[10];
    const int* is_causal = (const int*)d_in[11];
    float* out = (float*)d_out;

    float *qbuf, *kbuf, *vbuf, *abuf;
    cudaGetSymbolAddress((void**)&qbuf, g_Q);
    cudaGetSymbolAddress((void**)&kbuf, g_K);
    cudaGetSymbolAddress((void**)&vbuf, g_V);
    cudaGetSymbolAddress((void**)&abuf, g_A);

    const float qscale = 0.08838834764831845f;  // 1/sqrt(128)
    dim3 blk(256);

    // projections
    gemm_nt_bias<<<dim3(E_ / 128,  MR_ / 128), blk>>>(query, Wq, bq, qbuf, MR_, E_,  E_, qscale);
    gemm_nt_bias<<<dim3(KVE_ / 128, MR_ / 128), blk>>>(key,   Wk, bk, kbuf, MR_, KVE_, E_, 1.f);
    gemm_nt_bias<<<dim3(KVE_ / 128, MR_ / 128), blk>>>(value, Wv, bv, vbuf, MR_, KVE_, E_, 1.f);

    // attention
    size_t smem_bytes = (size_t)ATTN_SMEM_FLOATS * sizeof(float);
    cudaFuncSetAttribute(attn_kernel, cudaFuncAttributeMaxDynamicSharedMemorySize,
                         (int)smem_bytes);
    attn_kernel<<<dim3(N_ / AQB, B_ * HQ_), blk, smem_bytes>>>(qbuf, kbuf, vbuf, abuf, is_causal);

    // output projection
    gemm_nt_bias<<<dim3(E_ / 128, MR_ / 128), blk>>>(abuf, Wo, bo, out, MR_, E_, E_, 1.f);
}

// round 4
// speedup vs baseline: 1.6033x; 1.6033x over previous
#include <cuda_runtime.h>
#include <cuda_bf16.h>
#include <cstdint>
#include <math.h>

#define E_    2048
#define HQ_   16
#define HK_   4
#define D_    128
#define KVE_  512
#define B_    2
#define N_    2048
#define MR_   (B_ * N_)   // 4096 rows

// ---------------- scratch (no allocations allowed) ----------------
__device__ float g_Q[(size_t)MR_ * E_];    // fp32 q (pre-scaled), (b n, hq d)
__device__ float g_K[(size_t)MR_ * KVE_];
__device__ float g_V[(size_t)MR_ * KVE_];
__device__ float g_A[(size_t)MR_ * E_];    // attention out fp32

// split-bf16 operands (hi + lo)
__device__ __nv_bfloat16 s_q_hi[(size_t)MR_ * E_],  s_q_lo[(size_t)MR_ * E_];
__device__ __nv_bfloat16 s_k_hi[(size_t)MR_ * E_],  s_k_lo[(size_t)MR_ * E_];
__device__ __nv_bfloat16 s_v_hi[(size_t)MR_ * E_],  s_v_lo[(size_t)MR_ * E_];
__device__ __nv_bfloat16 s_a_hi[(size_t)MR_ * E_],  s_a_lo[(size_t)MR_ * E_];
__device__ __nv_bfloat16 w_q_hi[(size_t)E_ * E_],   w_q_lo[(size_t)E_ * E_];
__device__ __nv_bfloat16 w_k_hi[(size_t)KVE_ * E_], w_k_lo[(size_t)KVE_ * E_];
__device__ __nv_bfloat16 w_v_hi[(size_t)KVE_ * E_], w_v_lo[(size_t)KVE_ * E_];
__device__ __nv_bfloat16 w_o_hi[(size_t)E_ * E_],   w_o_lo[(size_t)E_ * E_];

// ================= helpers =================
__device__ __forceinline__ uint32_t smem_u32(const void* p) {
    uint32_t a;
    asm("{ .reg .u64 t; cvta.to.shared.u64 t, %1; cvt.u32.u64 %0, t; }" : "=r"(a) : "l"(p));
    return a;
}
__device__ __forceinline__ void cp16(uint32_t saddr, const void* g) {
    asm volatile("cp.async.cg.shared.global [%0], [%1], 16;" :: "r"(saddr), "l"(g));
}
#define CP_COMMIT() asm volatile("cp.async.commit_group;" ::: "memory")
#define CP_WAIT(n)  asm volatile("cp.async.wait_group %0;" :: "n"(n) : "memory")

__device__ __forceinline__ void ldm_x4(uint32_t* r, uint32_t addr) {
    asm volatile("ldmatrix.sync.aligned.m8n8.x4.shared.b16 {%0,%1,%2,%3}, [%4];"
                 : "=r"(r[0]), "=r"(r[1]), "=r"(r[2]), "=r"(r[3]) : "r"(addr));
}
__device__ __forceinline__ void mma_bf16(float* d, const uint32_t* a,
                                         uint32_t b0, uint32_t b1) {
    asm volatile(
        "mma.sync.aligned.m16n8k16.row.col.f32.bf16.bf16.f32 "
        "{%0,%1,%2,%3}, {%4,%5,%6,%7}, {%8,%9}, {%0,%1,%2,%3};"
        : "+f"(d[0]), "+f"(d[1]), "+f"(d[2]), "+f"(d[3])
        : "r"(a[0]), "r"(a[1]), "r"(a[2]), "r"(a[3]), "r"(b0), "r"(b1));
}

// ================= split fp32 -> bf16 hi/lo =================
__global__ void split_kernel(const float* __restrict__ x,
                             __nv_bfloat16* __restrict__ hi,
                             __nv_bfloat16* __restrict__ lo, int n4)
{
    int i = blockIdx.x * blockDim.x + threadIdx.x;
    if (i >= n4) return;
    float4 v = ((const float4*)x)[i];
    __nv_bfloat16 h0 = __float2bfloat16(v.x);
    __nv_bfloat16 h1 = __float2bfloat16(v.y);
    __nv_bfloat16 h2 = __float2bfloat16(v.z);
    __nv_bfloat16 h3 = __float2bfloat16(v.w);
    __nv_bfloat16 l0 = __float2bfloat16(v.x - __bfloat162float(h0));
    __nv_bfloat16 l1 = __float2bfloat16(v.y - __bfloat162float(h1));
    __nv_bfloat16 l2 = __float2bfloat16(v.z - __bfloat162float(h2));
    __nv_bfloat16 l3 = __float2bfloat16(v.w - __bfloat162float(h3));
    ((__nv_bfloat162*)hi)[i * 2]     = __halves2bfloat162(h0, h1);
    ((__nv_bfloat162*)hi)[i * 2 + 1] = __halves2bfloat162(h2, h3);
    ((__nv_bfloat162*)lo)[i * 2]     = __halves2bfloat162(l0, l1);
    ((__nv_bfloat162*)lo)[i * 2 + 1] = __halves2bfloat162(l2, l3);
}

// ================= HMMA NT GEMM (split-bf16 3-term) =================
// C[m,n] = (sum_k A[m,k]*W[n,k] + bias[n]) * scale
// CTA tile 128x128, K-chunk 32 bf16, cp.async double buffered.
#define BM 128
#define BN 128
#define BK 32
#define LDSB 80                      // bytes per smem row (64B data + 16B pad)
#define TILE_B (128 * LDSB)          // 10240
#define STAGE_B (4 * TILE_B)         // Ah, Al, Bh, Bl
#define GSMEM (2 * STAGE_B)          // 81920

__device__ __forceinline__ void load_chunk(uint32_t sb, int stage,
    const __nv_bfloat16* __restrict__ Ah, const __nv_bfloat16* __restrict__ Al,
    const __nv_bfloat16* __restrict__ Bh, const __nv_bfloat16* __restrict__ Bl,
    int K, int tid)
{
    const __nv_bfloat16* srcs[4] = { Ah, Al, Bh, Bl };
    uint32_t base = sb + stage * STAGE_B;
#pragma unroll
    for (int t = 0; t < 4; t++) {
#pragma unroll
        for (int it = 0; it < 2; it++) {
            int idx = tid + it * 256;      // 0..511
            int r = idx >> 2;              // 0..127
            int c = idx & 3;               // 0..3 (16B units)
            cp16(base + t * TILE_B + r * LDSB + c * 16,
                 srcs[t] + (size_t)r * K + c * 8);
        }
    }
}

__global__ void __launch_bounds__(256) gemm_hmma(
    const __nv_bfloat16* __restrict__ Ahi, const __nv_bfloat16* __restrict__ Alo,
    const __nv_bfloat16* __restrict__ Bhi, const __nv_bfloat16* __restrict__ Blo,
    const float* __restrict__ bias, float* __restrict__ C,
    int M, int Nn, int K, float scale)
{
    extern __shared__ char smem[];
    const uint32_t sb = smem_u32(smem);
    const int tid = threadIdx.x;
    const int lane = tid & 31;
    const int wid = tid >> 5;
    const int m0 = blockIdx.y * BM;
    const int n0 = blockIdx.x * BN;
    const int wm = wid & 1;        // 0..1  (64-row slab)
    const int wn = wid >> 1;       // 0..3  (32-col slab)

    const __nv_bfloat16* pAh = Ahi + (size_t)m0 * K;
    const __nv_bfloat16* pAl = Alo + (size_t)m0 * K;
    const __nv_bfloat16* pBh = Bhi + (size_t)n0 * K;
    const __nv_bfloat16* pBl = Blo + (size_t)n0 * K;

    float acc[4][4][4];
#pragma unroll
    for (int i = 0; i < 4; i++)
#pragma unroll
        for (int j = 0; j < 4; j++)
#pragma unroll
            for (int q = 0; q < 4; q++) acc[i][j][q] = 0.f;

    // ldmatrix per-lane offsets
    const uint32_t a_off = (uint32_t)((lane & 15) * LDSB + (lane >> 4) * 16);
    const uint32_t b_off = (uint32_t)(((lane & 7) + (lane >> 4) * 8) * LDSB
                                      + ((lane >> 3) & 1) * 16);

    const int nch = K >> 5;   // K / 32
    load_chunk(sb, 0, pAh, pAl, pBh, pBl, K, tid);
    CP_COMMIT();

    for (int c = 0; c < nch; c++) {
        const int st = c & 1;
        if (c + 1 < nch) {
            const size_t kb = (size_t)(c + 1) * BK;
            load_chunk(sb, st ^ 1, pAh + kb, pAl + kb, pBh + kb, pBl + kb, K, tid);
            CP_COMMIT();
            CP_WAIT(1);
        } else {
            CP_WAIT(0);
        }
        __syncthreads();

        const uint32_t stb = sb + st * STAGE_B;
        const uint32_t Ah_b = stb + 0 * TILE_B;
        const uint32_t Al_b = stb + 1 * TILE_B;
        const uint32_t Bh_b = stb + 2 * TILE_B;
        const uint32_t Bl_b = stb + 3 * TILE_B;

#pragma unroll
        for (int ks = 0; ks < 2; ks++) {
            const uint32_t kbyte = ks * 32;
            uint32_t aH[4][4], aL[4][4], bH[2][4], bL[2][4];
#pragma unroll
            for (int mi = 0; mi < 4; mi++)
                ldm_x4(aH[mi], Ah_b + (wm * 64 + mi * 16) * LDSB + kbyte + a_off);
#pragma unroll
            for (int nb = 0; nb < 2; nb++) {
                ldm_x4(bH[nb], Bh_b + (wn * 32 + nb * 16) * LDSB + kbyte + b_off);
                ldm_x4(bL[nb], Bl_b + (wn * 32 + nb * 16) * LDSB + kbyte + b_off);
            }
            // term1: Ahi * Bhi, term2: Ahi * Blo
#pragma unroll
            for (int mi = 0; mi < 4; mi++)
#pragma unroll
                for (int ni = 0; ni < 4; ni++) {
                    mma_bf16(acc[mi][ni], aH[mi], bH[ni >> 1][(ni & 1) * 2],
                                                   bH[ni >> 1][(ni & 1) * 2 + 1]);
                    mma_bf16(acc[mi][ni], aH[mi], bL[ni >> 1][(ni & 1) * 2],
                                                   bL[ni >> 1][(ni & 1) * 2 + 1]);
                }
            // term3: Alo * Bhi
#pragma unroll
            for (int mi = 0; mi < 4; mi++)
                ldm_x4(aL[mi], Al_b + (wm * 64 + mi * 16) * LDSB + kbyte + a_off);
#pragma unroll
            for (int mi = 0; mi < 4; mi++)
#pragma unroll
                for (int ni = 0; ni < 4; ni++)
                    mma_bf16(acc[mi][ni], aL[mi], bH[ni >> 1][(ni & 1) * 2],
                                                   bH[ni >> 1][(ni & 1) * 2 + 1]);
        }
        __syncthreads();
    }

    // ---- epilogue ----
    const int g = lane >> 2;
    const int cq = lane & 3;
#pragma unroll
    for (int mi = 0; mi < 4; mi++) {
#pragma unroll
        for (int ni = 0; ni < 4; ni++) {
            const int col = n0 + wn * 32 + ni * 8 + cq * 2;
            const float b0 = bias[col];
            const float b1 = bias[col + 1];
#pragma unroll
            for (int h = 0; h < 2; h++) {
                const int row = m0 + wm * 64 + mi * 16 + g + h * 8;
                float2 v;
                v.x = (acc[mi][ni][h * 2 + 0] + b0) * scale;
                v.y = (acc[mi][ni][h * 2 + 1] + b1) * scale;
                *(float2*)(C + (size_t)row * Nn + col) = v;
            }
        }
    }
}

// =================================================================
// Flash attention (fp32, online softmax) — unchanged (passing, R2).
// =================================================================
#define AQB 64
#define AKB 64
#define QK_STRIDE 68
#define ATTN_SMEM_FLOATS (128*QK_STRIDE + 128*QK_STRIDE + 64*128 + 64*QK_STRIDE)

__global__ void __launch_bounds__(256, 1) attn_kernel(
    const float* __restrict__ Qg, const float* __restrict__ Kg,
    const float* __restrict__ Vg, float* __restrict__ Og,
    const int* __restrict__ causal_p)
{
    extern __shared__ float sm[];
    float* Qs = sm;
    float* Ks = Qs + 128 * QK_STRIDE;
    float* Vs = Ks + 128 * QK_STRIDE;
    float* Ps = Vs + 64 * 128;

    const int tid = threadIdx.x;
    const int ty = tid >> 4;
    const int tx = tid & 15;
    const int qb = blockIdx.x;
    const int bh = blockIdx.y;
    const int b  = bh >> 4;
    const int hq = bh & 15;
    const int hk = hq >> 2;

    const int r0 = ty * 4;
    const int c0 = tx * 4;
    const int v0 = tx * 8;
    const bool causal = (causal_p[0] != 0);

    {
        const float* src = Qg + ((size_t)(b * N_ + qb * AQB)) * E_ + hq * D_;
#pragma unroll
        for (int it = 0; it < 8; it++) {
            int fi = tid + it * 256;
            int r  = fi >> 5;
            int dq = fi & 31;
            float4 v = *(const float4*)(src + (size_t)r * E_ + dq * 4);
            int d0 = dq * 4;
            float* q = Qs + d0 * QK_STRIDE + r;
            q[0 * QK_STRIDE] = v.x; q[1 * QK_STRIDE] = v.y;
            q[2 * QK_STRIDE] = v.z; q[3 * QK_STRIDE] = v.w;
        }
    }

    float m_i[4], l_i[4], o[4][8];
#pragma unroll
    for (int i = 0; i < 4; i++) { m_i[i] = -1e30f; l_i[i] = 0.f; }
#pragma unroll
    for (int i = 0; i < 4; i++)
#pragma unroll
        for (int j = 0; j < 8; j++) o[i][j] = 0.f;

    const int ktend = causal ? (qb + 1) : (N_ / AKB);

    for (int kt = 0; kt < ktend; kt++) {
        __syncthreads();
        {
            const float* ksrc = Kg + ((size_t)(b * N_ + kt * AKB)) * KVE_ + hk * D_;
            const float* vsrc = Vg + ((size_t)(b * N_ + kt * AKB)) * KVE_ + hk * D_;
#pragma unroll
            for (int it = 0; it < 8; it++) {
                int fi = tid + it * 256;
                int r  = fi >> 5;
                int dq = fi & 31;
                int d0 = dq * 4;
                float4 kv = *(const float4*)(ksrc + (size_t)r * KVE_ + dq * 4);
                float* p = Ks + d0 * QK_STRIDE + r;
                p[0 * QK_STRIDE] = kv.x; p[1 * QK_STRIDE] = kv.y;
                p[2 * QK_STRIDE] = kv.z; p[3 * QK_STRIDE] = kv.w;
                float4 vv = *(const float4*)(vsrc + (size_t)r * KVE_ + dq * 4);
                *(float4*)&Vs[r * 128 + d0] = vv;
            }
        }
        __syncthreads();

        float s[4][4];
#pragma unroll
        for (int i = 0; i < 4; i++)
#pragma unroll
            for (int j = 0; j < 4; j++) s[i][j] = 0.f;

#pragma unroll 16
        for (int dk = 0; dk < 128; dk++) {
            float qr[4], kr[4];
            *(float4*)qr = *(const float4*)(Qs + dk * QK_STRIDE + r0);
            *(float4*)kr = *(const float4*)(Ks + dk * QK_STRIDE + c0);
#pragma unroll
            for (int i = 0; i < 4; i++)
#pragma unroll
                for (int j = 0; j < 4; j++)
                    s[i][j] = fmaf(qr[i], kr[j], s[i][j]);
        }

        if (causal && kt == qb) {
            const int qrow = qb * AQB + r0;
            const int kcol = kt * AKB + c0;
#pragma unroll
            for (int i = 0; i < 4; i++)
#pragma unroll
                for (int j = 0; j < 4; j++)
                    if (kcol + j > qrow + i) s[i][j] = -1e30f;
        }

#pragma unroll
        for (int i = 0; i < 4; i++) {
            float rm = fmaxf(fmaxf(s[i][0], s[i][1]), fmaxf(s[i][2], s[i][3]));
            rm = fmaxf(rm, __shfl_xor_sync(0xffffffffu, rm, 1));
            rm = fmaxf(rm, __shfl_xor_sync(0xffffffffu, rm, 2));
            rm = fmaxf(rm, __shfl_xor_sync(0xffffffffu, rm, 4));
            rm = fmaxf(rm, __shfl_xor_sync(0xffffffffu, rm, 8));
            float mnew  = fmaxf(m_i[i], rm);
            float alpha = __expf(m_i[i] - mnew);
            m_i[i] = mnew;
            float rs = 0.f;
#pragma unroll
            for (int j = 0; j < 4; j++) {
                float p = __expf(s[i][j] - mnew);
                s[i][j] = p;
                rs += p;
            }
            rs += __shfl_xor_sync(0xffffffffu, rs, 1);
            rs += __shfl_xor_sync(0xffffffffu, rs, 2);
            rs += __shfl_xor_sync(0xffffffffu, rs, 4);
            rs += __shfl_xor_sync(0xffffffffu, rs, 8);
            l_i[i] = l_i[i] * alpha + rs;
#pragma unroll
            for (int j = 0; j < 8; j++) o[i][j] *= alpha;
#pragma unroll
            for (int j = 0; j < 4; j++)
                Ps[(c0 + j) * QK_STRIDE + (r0 + i)] = s[i][j];
        }
        __syncthreads();

#pragma unroll 8
        for (int ss = 0; ss < 64; ss++) {
            float pf[4], vf[8];
            *(float4*)pf    = *(const float4*)(Ps + ss * QK_STRIDE + r0);
            *(float4*)&vf[0] = *(const float4*)(Vs + ss * 128 + v0);
            *(float4*)&vf[4] = *(const float4*)(Vs + ss * 128 + v0 + 4);
#pragma unroll
            for (int i = 0; i < 4; i++)
#pragma unroll
                for (int j = 0; j < 8; j++)
                    o[i][j] = fmaf(pf[i], vf[j], o[i][j]);
        }
    }

#pragma unroll
    for (int i = 0; i < 4; i++) {
        float inv = 1.f / l_i[i];
        float* dst = Og + ((size_t)(b * N_ + qb * AQB + r0 + i)) * E_ + hq * D_ + v0;
        float4 t0, t1;
        t0.x = o[i][0] * inv; t0.y = o[i][1] * inv;
        t0.z = o[i][2] * inv; t0.w = o[i][3] * inv;
        t1.x = o[i][4] * inv; t1.y = o[i][5] * inv;
        t1.z = o[i][6] * inv; t1.w = o[i][7] * inv;
        *(float4*)(dst)     = t0;
        *(float4*)(dst + 4) = t1;
    }
}

// =================================================================
extern "C" void kernel_launch(void* const* d_in, const int* in_sizes, int n_in,
                              void* d_out, int out_size)
{
    const float* query = (const float*)d_in[0];
    const float* key   = (const float*)d_in[1];
    const float* value = (const float*)d_in[2];
    const float* Wq = (const float*)d_in[3];
    const float* bq = (const float*)d_in[4];
    const float* Wk = (const float*)d_in[5];
    const float* bk = (const float*)d_in[6];
    const float* Wv = (const float*)d_in[7];
    const float* bv = (const float*)d_in[8];
    const float* Wo = (const float*)d_in[9];
    const float* bo = (const float*)d_in[10];
    const int* is_causal = (const int*)d_in[11];
    float* out = (float*)d_out;

    float *qbuf, *kbuf, *vbuf, *abuf;
    cudaGetSymbolAddress((void**)&qbuf, g_Q);
    cudaGetSymbolAddress((void**)&kbuf, g_K);
    cudaGetSymbolAddress((void**)&vbuf, g_V);
    cudaGetSymbolAddress((void**)&abuf, g_A);

    __nv_bfloat16 *qh, *ql, *kh, *kl, *vh, *vl, *ah, *al;
    __nv_bfloat16 *wqh, *wql, *wkh, *wkl, *wvh, *wvl, *woh, *wol;
    cudaGetSymbolAddress((void**)&qh, s_q_hi);  cudaGetSymbolAddress((void**)&ql, s_q_lo);
    cudaGetSymbolAddress((void**)&kh, s_k_hi);  cudaGetSymbolAddress((void**)&kl, s_k_lo);
    cudaGetSymbolAddress((void**)&vh, s_v_hi);  cudaGetSymbolAddress((void**)&vl, s_v_lo);
    cudaGetSymbolAddress((void**)&ah, s_a_hi);  cudaGetSymbolAddress((void**)&al, s_a_lo);
    cudaGetSymbolAddress((void**)&wqh, w_q_hi); cudaGetSymbolAddress((void**)&wql, w_q_lo);
    cudaGetSymbolAddress((void**)&wkh, w_k_hi); cudaGetSymbolAddress((void**)&wkl, w_k_lo);
    cudaGetSymbolAddress((void**)&wvh, w_v_hi); cudaGetSymbolAddress((void**)&wvl, w_v_lo);
    cudaGetSymbolAddress((void**)&woh, w_o_hi); cudaGetSymbolAddress((void**)&wol, w_o_lo);

    const float qscale = 0.08838834764831845f;  // 1/sqrt(128)

    // ---- split conversions ----
    const int actN4 = (MR_ * E_) / 4;
    const int wqN4  = (E_ * E_) / 4;
    const int wkN4  = (KVE_ * E_) / 4;
    split_kernel<<<(actN4 + 255) / 256, 256>>>(query, qh, ql, actN4);
    split_kernel<<<(actN4 + 255) / 256, 256>>>(key,   kh, kl, actN4);
    split_kernel<<<(actN4 + 255) / 256, 256>>>(value, vh, vl, actN4);
    split_kernel<<<(wqN4 + 255) / 256, 256>>>(Wq, wqh, wql, wqN4);
    split_kernel<<<(wkN4 + 255) / 256, 256>>>(Wk, wkh, wkl, wkN4);
    split_kernel<<<(wkN4 + 255) / 256, 256>>>(Wv, wvh, wvl, wkN4);
    split_kernel<<<(wqN4 + 255) / 256, 256>>>(Wo, woh, wol, wqN4);

    // ---- HMMA projection GEMMs ----
    cudaFuncSetAttribute(gemm_hmma, cudaFuncAttributeMaxDynamicSharedMemorySize, GSMEM);
    gemm_hmma<<<dim3(E_ / BN,  MR_ / BM), 256, GSMEM>>>(qh, ql, wqh, wql, bq, qbuf, MR_, E_,  E_, qscale);
    gemm_hmma<<<dim3(KVE_ / BN, MR_ / BM), 256, GSMEM>>>(kh, kl, wkh, wkl, bk, kbuf, MR_, KVE_, E_, 1.f);
    gemm_hmma<<<dim3(KVE_ / BN, MR_ / BM), 256, GSMEM>>>(vh, vl, wvh, wvl, bv, vbuf, MR_, KVE_, E_, 1.f);

    // ---- attention (fp32 SIMT, unchanged) ----
    size_t smem_bytes = (size_t)ATTN_SMEM_FLOATS * sizeof(float);
    cudaFuncSetAttribute(attn_kernel, cudaFuncAttributeMaxDynamicSharedMemorySize,
                         (int)smem_bytes);
    attn_kernel<<<dim3(N_ / AQB, B_ * HQ_), 256, smem_bytes>>>(qbuf, kbuf, vbuf, abuf, is_causal);

    // ---- split attention output, O projection ----
    split_kernel<<<(actN4 + 255) / 256, 256>>>(abuf, ah, al, actN4);
    gemm_hmma<<<dim3(E_ / BN, MR_ / BM), 256, GSMEM>>>(ah, al, woh, wol, bo, out, MR_, E_, E_, 1.f);
}

// round 5
// speedup vs baseline: 3.2312x; 2.0154x over previous
#include <cuda_runtime.h>
#include <cuda_bf16.h>
#include <cuda_fp16.h>
#include <cstdint>
#include <math.h>

#define E_    2048
#define HQ_   16
#define HK_   4
#define D_    128
#define KVE_  512
#define B_    2
#define N_    2048
#define MR_   (B_ * N_)   // 4096 rows

// ---------------- scratch (no allocations allowed) ----------------
// input splits (bf16 hi/lo) for GEMM A operands
__device__ __nv_bfloat16 s_q_hi[(size_t)MR_ * E_],  s_q_lo[(size_t)MR_ * E_];
__device__ __nv_bfloat16 s_k_hi[(size_t)MR_ * E_],  s_k_lo[(size_t)MR_ * E_];
__device__ __nv_bfloat16 s_v_hi[(size_t)MR_ * E_],  s_v_lo[(size_t)MR_ * E_];
// weight splits
__device__ __nv_bfloat16 w_q_hi[(size_t)E_ * E_],   w_q_lo[(size_t)E_ * E_];
__device__ __nv_bfloat16 w_k_hi[(size_t)KVE_ * E_], w_k_lo[(size_t)KVE_ * E_];
__device__ __nv_bfloat16 w_v_hi[(size_t)KVE_ * E_], w_v_lo[(size_t)KVE_ * E_];
__device__ __nv_bfloat16 w_o_hi[(size_t)E_ * E_],   w_o_lo[(size_t)E_ * E_];
// projection outputs for attention
__device__ __nv_bfloat16 q_hi[(size_t)MR_ * E_],   q_lo[(size_t)MR_ * E_];    // pre-scaled
__device__ __nv_bfloat16 k_hi[(size_t)MR_ * KVE_], k_lo[(size_t)MR_ * KVE_];
__device__ __half        v_f16[(size_t)MR_ * KVE_];
// attention output (bf16 hi/lo for O-proj)
__device__ __nv_bfloat16 a_hi[(size_t)MR_ * E_],   a_lo[(size_t)MR_ * E_];

// ================= helpers =================
__device__ __forceinline__ uint32_t smem_u32(const void* p) {
    uint32_t a;
    asm("{ .reg .u64 t; cvta.to.shared.u64 t, %1; cvt.u32.u64 %0, t; }" : "=r"(a) : "l"(p));
    return a;
}
__device__ __forceinline__ void cp16(uint32_t saddr, const void* g) {
    asm volatile("cp.async.cg.shared.global [%0], [%1], 16;" :: "r"(saddr), "l"(g));
}
#define CP_COMMIT() asm volatile("cp.async.commit_group;" ::: "memory")
#define CP_WAIT(n)  asm volatile("cp.async.wait_group %0;" :: "n"(n) : "memory")

__device__ __forceinline__ void ldm_x4(uint32_t* r, uint32_t addr) {
    asm volatile("ldmatrix.sync.aligned.m8n8.x4.shared.b16 {%0,%1,%2,%3}, [%4];"
                 : "=r"(r[0]), "=r"(r[1]), "=r"(r[2]), "=r"(r[3]) : "r"(addr));
}
__device__ __forceinline__ void ldm_x4_t(uint32_t* r, uint32_t addr) {
    asm volatile("ldmatrix.sync.aligned.m8n8.x4.trans.shared.b16 {%0,%1,%2,%3}, [%4];"
                 : "=r"(r[0]), "=r"(r[1]), "=r"(r[2]), "=r"(r[3]) : "r"(addr));
}
__device__ __forceinline__ void mma_bf16(float* d, const uint32_t* a,
                                         uint32_t b0, uint32_t b1) {
    asm volatile(
        "mma.sync.aligned.m16n8k16.row.col.f32.bf16.bf16.f32 "
        "{%0,%1,%2,%3}, {%4,%5,%6,%7}, {%8,%9}, {%0,%1,%2,%3};"
        : "+f"(d[0]), "+f"(d[1]), "+f"(d[2]), "+f"(d[3])
        : "r"(a[0]), "r"(a[1]), "r"(a[2]), "r"(a[3]), "r"(b0), "r"(b1));
}
__device__ __forceinline__ void mma_f16(float* d, const uint32_t* a,
                                        uint32_t b0, uint32_t b1) {
    asm volatile(
        "mma.sync.aligned.m16n8k16.row.col.f32.f16.f16.f32 "
        "{%0,%1,%2,%3}, {%4,%5,%6,%7}, {%8,%9}, {%0,%1,%2,%3};"
        : "+f"(d[0]), "+f"(d[1]), "+f"(d[2]), "+f"(d[3])
        : "r"(a[0]), "r"(a[1]), "r"(a[2]), "r"(a[3]), "r"(b0), "r"(b1));
}
__device__ __forceinline__ void split_store2(__nv_bfloat16* hi, __nv_bfloat16* lo,
                                             size_t off, float y0, float y1) {
    __nv_bfloat16 h0 = __float2bfloat16(y0);
    __nv_bfloat16 h1 = __float2bfloat16(y1);
    __nv_bfloat16 l0 = __float2bfloat16(y0 - __bfloat162float(h0));
    __nv_bfloat16 l1 = __float2bfloat16(y1 - __bfloat162float(h1));
    *(__nv_bfloat162*)(hi + off) = __halves2bfloat162(h0, h1);
    *(__nv_bfloat162*)(lo + off) = __halves2bfloat162(l0, l1);
}

// ================= split fp32 -> bf16 hi/lo =================
__global__ void split_kernel(const float* __restrict__ x,
                             __nv_bfloat16* __restrict__ hi,
                             __nv_bfloat16* __restrict__ lo, int n4)
{
    int i = blockIdx.x * blockDim.x + threadIdx.x;
    if (i >= n4) return;
    float4 v = ((const float4*)x)[i];
    __nv_bfloat16 h0 = __float2bfloat16(v.x);
    __nv_bfloat16 h1 = __float2bfloat16(v.y);
    __nv_bfloat16 h2 = __float2bfloat16(v.z);
    __nv_bfloat16 h3 = __float2bfloat16(v.w);
    __nv_bfloat16 l0 = __float2bfloat16(v.x - __bfloat162float(h0));
    __nv_bfloat16 l1 = __float2bfloat16(v.y - __bfloat162float(h1));
    __nv_bfloat16 l2 = __float2bfloat16(v.z - __bfloat162float(h2));
    __nv_bfloat16 l3 = __float2bfloat16(v.w - __bfloat162float(h3));
    ((__nv_bfloat162*)hi)[i * 2]     = __halves2bfloat162(h0, h1);
    ((__nv_bfloat162*)hi)[i * 2 + 1] = __halves2bfloat162(h2, h3);
    ((__nv_bfloat162*)lo)[i * 2]     = __halves2bfloat162(l0, l1);
    ((__nv_bfloat162*)lo)[i * 2 + 1] = __halves2bfloat162(l2, l3);
}

// ================= HMMA NT GEMM (split-bf16 3-term) =================
// MODE 0: fp32 out; MODE 1: bf16 hi/lo out; MODE 2: fp16 out.
#define BM 128
#define BN 128
#define BK 32
#define LDSB 80
#define TILE_B (128 * LDSB)
#define STAGE_B (4 * TILE_B)
#define GSMEM (2 * STAGE_B)

__device__ __forceinline__ void load_chunk(uint32_t sb, int stage,
    const __nv_bfloat16* __restrict__ Ah, const __nv_bfloat16* __restrict__ Al,
    const __nv_bfloat16* __restrict__ Bh, const __nv_bfloat16* __restrict__ Bl,
    int K, int tid)
{
    const __nv_bfloat16* srcs[4] = { Ah, Al, Bh, Bl };
    uint32_t base = sb + stage * STAGE_B;
#pragma unroll
    for (int t = 0; t < 4; t++) {
#pragma unroll
        for (int it = 0; it < 2; it++) {
            int idx = tid + it * 256;
            int r = idx >> 2;
            int c = idx & 3;
            cp16(base + t * TILE_B + r * LDSB + c * 16,
                 srcs[t] + (size_t)r * K + c * 8);
        }
    }
}

template <int MODE>
__global__ void __launch_bounds__(256) gemm_hmma(
    const __nv_bfloat16* __restrict__ Ahi, const __nv_bfloat16* __restrict__ Alo,
    const __nv_bfloat16* __restrict__ Bhi, const __nv_bfloat16* __restrict__ Blo,
    const float* __restrict__ bias,
    float* __restrict__ C, __nv_bfloat16* __restrict__ Chi,
    __nv_bfloat16* __restrict__ Clo, __half* __restrict__ Cf,
    int M, int Nn, int K, float scale)
{
    extern __shared__ char smem[];
    const uint32_t sb = smem_u32(smem);
    const int tid = threadIdx.x;
    const int lane = tid & 31;
    const int wid = tid >> 5;
    const int m0 = blockIdx.y * BM;
    const int n0 = blockIdx.x * BN;
    const int wm = wid & 1;
    const int wn = wid >> 1;

    const __nv_bfloat16* pAh = Ahi + (size_t)m0 * K;
    const __nv_bfloat16* pAl = Alo + (size_t)m0 * K;
    const __nv_bfloat16* pBh = Bhi + (size_t)n0 * K;
    const __nv_bfloat16* pBl = Blo + (size_t)n0 * K;

    float acc[4][4][4];
#pragma unroll
    for (int i = 0; i < 4; i++)
#pragma unroll
        for (int j = 0; j < 4; j++)
#pragma unroll
            for (int q = 0; q < 4; q++) acc[i][j][q] = 0.f;

    const uint32_t a_off = (uint32_t)((lane & 15) * LDSB + (lane >> 4) * 16);
    const uint32_t b_off = (uint32_t)(((lane & 7) + (lane >> 4) * 8) * LDSB
                                      + ((lane >> 3) & 1) * 16);

    const int nch = K >> 5;
    load_chunk(sb, 0, pAh, pAl, pBh, pBl, K, tid);
    CP_COMMIT();

    for (int c = 0; c < nch; c++) {
        const int st = c & 1;
        if (c + 1 < nch) {
            const size_t kb = (size_t)(c + 1) * BK;
            load_chunk(sb, st ^ 1, pAh + kb, pAl + kb, pBh + kb, pBl + kb, K, tid);
            CP_COMMIT();
            CP_WAIT(1);
        } else {
            CP_WAIT(0);
        }
        __syncthreads();

        const uint32_t stb = sb + st * STAGE_B;
        const uint32_t Ah_b = stb + 0 * TILE_B;
        const uint32_t Al_b = stb + 1 * TILE_B;
        const uint32_t Bh_b = stb + 2 * TILE_B;
        const uint32_t Bl_b = stb + 3 * TILE_B;

#pragma unroll
        for (int ks = 0; ks < 2; ks++) {
            const uint32_t kbyte = ks * 32;
            uint32_t aH[4][4], aL[4][4], bH[2][4], bL[2][4];
#pragma unroll
            for (int mi = 0; mi < 4; mi++)
                ldm_x4(aH[mi], Ah_b + (wm * 64 + mi * 16) * LDSB + kbyte + a_off);
#pragma unroll
            for (int nb = 0; nb < 2; nb++) {
                ldm_x4(bH[nb], Bh_b + (wn * 32 + nb * 16) * LDSB + kbyte + b_off);
                ldm_x4(bL[nb], Bl_b + (wn * 32 + nb * 16) * LDSB + kbyte + b_off);
            }
#pragma unroll
            for (int mi = 0; mi < 4; mi++)
#pragma unroll
                for (int ni = 0; ni < 4; ni++) {
                    mma_bf16(acc[mi][ni], aH[mi], bH[ni >> 1][(ni & 1) * 2],
                                                   bH[ni >> 1][(ni & 1) * 2 + 1]);
                    mma_bf16(acc[mi][ni], aH[mi], bL[ni >> 1][(ni & 1) * 2],
                                                   bL[ni >> 1][(ni & 1) * 2 + 1]);
                }
#pragma unroll
            for (int mi = 0; mi < 4; mi++)
                ldm_x4(aL[mi], Al_b + (wm * 64 + mi * 16) * LDSB + kbyte + a_off);
#pragma unroll
            for (int mi = 0; mi < 4; mi++)
#pragma unroll
                for (int ni = 0; ni < 4; ni++)
                    mma_bf16(acc[mi][ni], aL[mi], bH[ni >> 1][(ni & 1) * 2],
                                                   bH[ni >> 1][(ni & 1) * 2 + 1]);
        }
        __syncthreads();
    }

    // ---- epilogue ----
    const int g = lane >> 2;
    const int cq = lane & 3;
#pragma unroll
    for (int mi = 0; mi < 4; mi++) {
#pragma unroll
        for (int ni = 0; ni < 4; ni++) {
            const int col = n0 + wn * 32 + ni * 8 + cq * 2;
            const float b0 = bias[col];
            const float b1 = bias[col + 1];
#pragma unroll
            for (int h = 0; h < 2; h++) {
                const int row = m0 + wm * 64 + mi * 16 + g + h * 8;
                const float y0 = (acc[mi][ni][h * 2 + 0] + b0) * scale;
                const float y1 = (acc[mi][ni][h * 2 + 1] + b1) * scale;
                const size_t off = (size_t)row * Nn + col;
                if (MODE == 0) {
                    float2 v; v.x = y0; v.y = y1;
                    *(float2*)(C + off) = v;
                } else if (MODE == 1) {
                    split_store2(Chi, Clo, off, y0, y1);
                } else {
                    *(__half2*)(Cf + off) = __floats2half2_rn(y0, y1);
                }
            }
        }
    }
}

// =================================================================
// HMMA flash attention.
// CTA: 128 q-rows x one (b, hq). 8 warps, each owns 16 rows.
// S = QK^T in bf16 3-term; PV in fp16 2-term (P split, V single).
// =================================================================
#define QSTR 272                       // bytes per smem row (256 data + 16 pad)
#define AT_QH   0
#define AT_QL   (128 * QSTR)           // 34816
#define AT_KV0  (2 * 128 * QSTR)       // 69632
#define AT_STG  (3 * 64 * QSTR)        // 52224 per stage (Kh, Kl, V)
#define AT_KH   0
#define AT_KL   (64 * QSTR)
#define AT_VV   (2 * 64 * QSTR)
#define AT_SMEM (AT_KV0 + 2 * AT_STG)  // 174080

__device__ __forceinline__ void attn_load_kv(uint32_t sb, int stage, int b, int hk,
                                             int kt, const __nv_bfloat16* kh,
                                             const __nv_bfloat16* kl,
                                             const __half* vv, int tid)
{
    const uint32_t base = sb + AT_KV0 + stage * AT_STG;
    const size_t rowg = (size_t)(b * N_ + kt * 64);
#pragma unroll
    for (int it = 0; it < 12; it++) {
        int idx = tid + it * 256;              // 0..3071
        int buf = idx >> 10;                   // 0: kh, 1: kl, 2: v
        int r = (idx & 1023) >> 4;             // 0..63
        int c = idx & 15;                      // 16B chunk
        uint32_t dst = base + (buf == 0 ? AT_KH : (buf == 1 ? AT_KL : AT_VV))
                     + r * QSTR + c * 16;
        if (buf == 0)
            cp16(dst, kh + (rowg + r) * KVE_ + hk * D_ + c * 8);
        else if (buf == 1)
            cp16(dst, kl + (rowg + r) * KVE_ + hk * D_ + c * 8);
        else
            cp16(dst, vv + (rowg + r) * KVE_ + hk * D_ + c * 8);
    }
}

__global__ void __launch_bounds__(256, 1) attn_mma(
    const __nv_bfloat16* __restrict__ qh, const __nv_bfloat16* __restrict__ ql,
    const __nv_bfloat16* __restrict__ kh, const __nv_bfloat16* __restrict__ kl,
    const __half* __restrict__ vv,
    __nv_bfloat16* __restrict__ ah, __nv_bfloat16* __restrict__ al,
    const int* __restrict__ causal_p)
{
    extern __shared__ char smem[];
    const uint32_t sb = smem_u32(smem);
    const int tid = threadIdx.x;
    const int lane = tid & 31;
    const int wid = tid >> 5;
    const int qt = blockIdx.x;          // 0..15
    const int bh = blockIdx.y;          // 0..31
    const int b  = bh >> 4;
    const int hq = bh & 15;
    const int hk = hq >> 2;
    const int wr = wid * 16;            // warp row base within CTA
    const int g = lane >> 2;
    const int cq = lane & 3;
    const bool causal = (causal_p[0] != 0);

    const uint32_t a_off = (uint32_t)((lane & 15) * QSTR + (lane >> 4) * 16);
    const uint32_t b_off = (uint32_t)(((lane & 7) + (lane >> 4) * 8) * QSTR
                                      + ((lane >> 3) & 1) * 16);

    // ---- load Q tile (128 x 128 bf16 hi/lo) ----
    {
        const size_t rowg = (size_t)(b * N_ + qt * 128);
#pragma unroll
        for (int it = 0; it < 16; it++) {
            int idx = tid + it * 256;           // 0..4095
            int buf = idx >> 11;                // 0: qh, 1: ql
            int r = (idx & 2047) >> 4;          // 0..127
            int c = idx & 15;
            uint32_t dst = sb + (buf ? AT_QL : AT_QH) + r * QSTR + c * 16;
            const __nv_bfloat16* src = buf ? ql : qh;
            cp16(dst, src + (rowg + r) * E_ + hq * D_ + c * 8);
        }
    }
    attn_load_kv(sb, 0, b, hk, 0, kh, kl, vv, tid);
    CP_COMMIT();

    float m_i[2] = { -1e30f, -1e30f };
    float l_i[2] = { 0.f, 0.f };
    float o[16][4];
#pragma unroll
    for (int i = 0; i < 16; i++)
#pragma unroll
        for (int j = 0; j < 4; j++) o[i][j] = 0.f;

    const int ktend = causal ? 2 * (qt + 1) : (N_ / 64);

    for (int kt = 0; kt < ktend; kt++) {
        const int st = kt & 1;
        if (kt + 1 < ktend) {
            attn_load_kv(sb, st ^ 1, b, hk, kt + 1, kh, kl, vv, tid);
            CP_COMMIT();
            CP_WAIT(1);
        } else {
            CP_WAIT(0);
        }
        __syncthreads();

        const uint32_t KHb = sb + AT_KV0 + st * AT_STG + AT_KH;
        const uint32_t KLb = sb + AT_KV0 + st * AT_STG + AT_KL;
        const uint32_t VVb = sb + AT_KV0 + st * AT_STG + AT_VV;

        // ---- S = Q K^T (16 rows x 64 cols per warp), bf16 3-term ----
        float s[8][4];
#pragma unroll
        for (int i = 0; i < 8; i++)
#pragma unroll
            for (int j = 0; j < 4; j++) s[i][j] = 0.f;

#pragma unroll
        for (int ks = 0; ks < 8; ks++) {
            const uint32_t kb = ks * 32;
            uint32_t aH[4], aL[4];
            ldm_x4(aH, sb + AT_QH + wr * QSTR + kb + a_off);
            ldm_x4(aL, sb + AT_QL + wr * QSTR + kb + a_off);
#pragma unroll
            for (int t = 0; t < 4; t++) {
                uint32_t bh4[4], bl4[4];
                ldm_x4(bh4, KHb + (t * 16) * QSTR + kb + b_off);
                ldm_x4(bl4, KLb + (t * 16) * QSTR + kb + b_off);
                mma_bf16(s[2 * t],     aH, bh4[0], bh4[1]);
                mma_bf16(s[2 * t],     aH, bl4[0], bl4[1]);
                mma_bf16(s[2 * t],     aL, bh4[0], bh4[1]);
                mma_bf16(s[2 * t + 1], aH, bh4[2], bh4[3]);
                mma_bf16(s[2 * t + 1], aH, bl4[2], bl4[3]);
                mma_bf16(s[2 * t + 1], aL, bh4[2], bh4[3]);
            }
        }

        // ---- causal mask ----
        const int row0 = qt * 128 + wr + g;
        if (causal && (kt * 64 + 63 > qt * 128 + wr)) {
            const int col0 = kt * 64 + 2 * cq;
#pragma unroll
            for (int ni = 0; ni < 8; ni++)
#pragma unroll
                for (int j = 0; j < 4; j++) {
                    int row = row0 + (j >> 1) * 8;
                    int col = col0 + ni * 8 + (j & 1);
                    if (col > row) s[ni][j] = -1e30f;
                }
        }

        // ---- online softmax (per row; quad lanes share a row) ----
#pragma unroll
        for (int h = 0; h < 2; h++) {
            float rm = -1e30f;
#pragma unroll
            for (int ni = 0; ni < 8; ni++)
                rm = fmaxf(rm, fmaxf(s[ni][2 * h], s[ni][2 * h + 1]));
            rm = fmaxf(rm, __shfl_xor_sync(0xffffffffu, rm, 1));
            rm = fmaxf(rm, __shfl_xor_sync(0xffffffffu, rm, 2));
            const float mn = fmaxf(m_i[h], rm);
            const float alpha = __expf(m_i[h] - mn);
            m_i[h] = mn;
            float rs = 0.f;
#pragma unroll
            for (int ni = 0; ni < 8; ni++) {
                float e0 = __expf(s[ni][2 * h]     - mn);
                float e1 = __expf(s[ni][2 * h + 1] - mn);
                s[ni][2 * h] = e0; s[ni][2 * h + 1] = e1;
                rs += e0 + e1;
            }
            rs += __shfl_xor_sync(0xffffffffu, rs, 1);
            rs += __shfl_xor_sync(0xffffffffu, rs, 2);
            l_i[h] = l_i[h] * alpha + rs;
#pragma unroll
            for (int np = 0; np < 16; np++) {
                o[np][2 * h]     *= alpha;
                o[np][2 * h + 1] *= alpha;
            }
        }

        // ---- O += P V (fp16, P split 2-term) ----
#pragma unroll
        for (int ks = 0; ks < 4; ks++) {
            uint32_t aPh[4], aPl[4];
#pragma unroll
            for (int q = 0; q < 4; q++) {
                const int ni = 2 * ks + (q >> 1);
                const int j0 = (q & 1) * 2;
                float e0 = s[ni][j0], e1 = s[ni][j0 + 1];
                __half2 hh = __floats2half2_rn(e0, e1);
                aPh[q] = *(uint32_t*)&hh;
                float2 hf = __half22float2(hh);
                __half2 ll = __floats2half2_rn(e0 - hf.x, e1 - hf.y);
                aPl[q] = *(uint32_t*)&ll;
            }
#pragma unroll
            for (int np = 0; np < 8; np++) {
                uint32_t bv[4];
                ldm_x4_t(bv, VVb + (ks * 16) * QSTR + np * 32 + a_off);
                mma_f16(o[2 * np],     aPh, bv[0], bv[1]);
                mma_f16(o[2 * np],     aPl, bv[0], bv[1]);
                mma_f16(o[2 * np + 1], aPh, bv[2], bv[3]);
                mma_f16(o[2 * np + 1], aPl, bv[2], bv[3]);
            }
        }
        __syncthreads();
    }

    // ---- epilogue: normalize, split to bf16 hi/lo ----
    const float inv0 = 1.f / l_i[0];
    const float inv1 = 1.f / l_i[1];
    const size_t rowa = (size_t)(b * N_ + qt * 128 + wr + g);
    const int colb = hq * D_ + 2 * cq;
#pragma unroll
    for (int np = 0; np < 16; np++) {
        const size_t off0 = rowa * E_ + colb + np * 8;
        split_store2(ah, al, off0, o[np][0] * inv0, o[np][1] * inv0);
        const size_t off1 = (rowa + 8) * E_ + colb + np * 8;
        split_store2(ah, al, off1, o[np][2] * inv1, o[np][3] * inv1);
    }
}

// =================================================================
extern "C" void kernel_launch(void* const* d_in, const int* in_sizes, int n_in,
                              void* d_out, int out_size)
{
    const float* query = (const float*)d_in[0];
    const float* key   = (const float*)d_in[1];
    const float* value = (const float*)d_in[2];
    const float* Wq = (const float*)d_in[3];
    const float* bq = (const float*)d_in[4];
    const float* Wk = (const float*)d_in[5];
    const float* bk = (const float*)d_in[6];
    const float* Wv = (const float*)d_in[7];
    const float* bv = (const float*)d_in[8];
    const float* Wo = (const float*)d_in[9];
    const float* bo = (const float*)d_in[10];
    const int* is_causal = (const int*)d_in[11];
    float* out = (float*)d_out;

    __nv_bfloat16 *sqh, *sql, *skh, *skl, *svh, *svl;
    __nv_bfloat16 *wqh, *wql, *wkh, *wkl, *wvh, *wvl, *woh, *wol;
    __nv_bfloat16 *qhp, *qlp, *khp, *klp, *ahp, *alp;
    __half *vfp;
    cudaGetSymbolAddress((void**)&sqh, s_q_hi);  cudaGetSymbolAddress((void**)&sql, s_q_lo);
    cudaGetSymbolAddress((void**)&skh, s_k_hi);  cudaGetSymbolAddress((void**)&skl, s_k_lo);
    cudaGetSymbolAddress((void**)&svh, s_v_hi);  cudaGetSymbolAddress((void**)&svl, s_v_lo);
    cudaGetSymbolAddress((void**)&wqh, w_q_hi);  cudaGetSymbolAddress((void**)&wql, w_q_lo);
    cudaGetSymbolAddress((void**)&wkh, w_k_hi);  cudaGetSymbolAddress((void**)&wkl, w_k_lo);
    cudaGetSymbolAddress((void**)&wvh, w_v_hi);  cudaGetSymbolAddress((void**)&wvl, w_v_lo);
    cudaGetSymbolAddress((void**)&woh, w_o_hi);  cudaGetSymbolAddress((void**)&wol, w_o_lo);
    cudaGetSymbolAddress((void**)&qhp, q_hi);    cudaGetSymbolAddress((void**)&qlp, q_lo);
    cudaGetSymbolAddress((void**)&khp, k_hi);    cudaGetSymbolAddress((void**)&klp, k_lo);
    cudaGetSymbolAddress((void**)&vfp, v_f16);
    cudaGetSymbolAddress((void**)&ahp, a_hi);    cudaGetSymbolAddress((void**)&alp, a_lo);

    const float qscale = 0.08838834764831845f;  // 1/sqrt(128)

    // ---- input splits ----
    const int actN4 = (MR_ * E_) / 4;
    const int wqN4  = (E_ * E_) / 4;
    const int wkN4  = (KVE_ * E_) / 4;
    split_kernel<<<(actN4 + 255) / 256, 256>>>(query, sqh, sql, actN4);
    split_kernel<<<(actN4 + 255) / 256, 256>>>(key,   skh, skl, actN4);
    split_kernel<<<(actN4 + 255) / 256, 256>>>(value, svh, svl, actN4);
    split_kernel<<<(wqN4 + 255) / 256, 256>>>(Wq, wqh, wql, wqN4);
    split_kernel<<<(wkN4 + 255) / 256, 256>>>(Wk, wkh, wkl, wkN4);
    split_kernel<<<(wkN4 + 255) / 256, 256>>>(Wv, wvh, wvl, wkN4);
    split_kernel<<<(wqN4 + 255) / 256, 256>>>(Wo, woh, wol, wqN4);

    // ---- projection GEMMs with fused precision epilogues ----
    cudaFuncSetAttribute(gemm_hmma<0>, cudaFuncAttributeMaxDynamicSharedMemorySize, GSMEM);
    cudaFuncSetAttribute(gemm_hmma<1>, cudaFuncAttributeMaxDynamicSharedMemorySize, GSMEM);
    cudaFuncSetAttribute(gemm_hmma<2>, cudaFuncAttributeMaxDynamicSharedMemorySize, GSMEM);
    gemm_hmma<1><<<dim3(E_ / BN,  MR_ / BM), 256, GSMEM>>>(
        sqh, sql, wqh, wql, bq, nullptr, qhp, qlp, nullptr, MR_, E_,  E_, qscale);
    gemm_hmma<1><<<dim3(KVE_ / BN, MR_ / BM), 256, GSMEM>>>(
        skh, skl, wkh, wkl, bk, nullptr, khp, klp, nullptr, MR_, KVE_, E_, 1.f);
    gemm_hmma<2><<<dim3(KVE_ / BN, MR_ / BM), 256, GSMEM>>>(
        svh, svl, wvh, wvl, bv, nullptr, nullptr, nullptr, vfp, MR_, KVE_, E_, 1.f);

    // ---- HMMA flash attention ----
    cudaFuncSetAttribute(attn_mma, cudaFuncAttributeMaxDynamicSharedMemorySize, AT_SMEM);
    attn_mma<<<dim3(N_ / 128, B_ * HQ_), 256, AT_SMEM>>>(
        qhp, qlp, khp, klp, vfp, ahp, alp, is_causal);

    // ---- O projection (fp32 out) ----
    gemm_hmma<0><<<dim3(E_ / BN, MR_ / BM), 256, GSMEM>>>(
        ahp, alp, woh, wol, bo, out, nullptr, nullptr, nullptr, MR_, E_, E_, 1.f);
}

// round 6
// speedup vs baseline: 3.4234x; 1.0595x over previous
#include <cuda_runtime.h>
#include <cuda_bf16.h>
#include <cuda_fp16.h>
#include <cstdint>
#include <math.h>

#define E_    2048
#define HQ_   16
#define HK_   4
#define D_    128
#define KVE_  512
#define B_    2
#define N_    2048
#define MR_   (B_ * N_)   // 4096 rows

// ---------------- scratch (no allocations allowed) ----------------
__device__ __nv_bfloat16 s_q_hi[(size_t)MR_ * E_],  s_q_lo[(size_t)MR_ * E_];
__device__ __nv_bfloat16 s_k_hi[(size_t)MR_ * E_],  s_k_lo[(size_t)MR_ * E_];
__device__ __nv_bfloat16 s_v_hi[(size_t)MR_ * E_],  s_v_lo[(size_t)MR_ * E_];
__device__ __nv_bfloat16 w_q_hi[(size_t)E_ * E_],   w_q_lo[(size_t)E_ * E_];
__device__ __nv_bfloat16 w_k_hi[(size_t)KVE_ * E_], w_k_lo[(size_t)KVE_ * E_];
__device__ __nv_bfloat16 w_v_hi[(size_t)KVE_ * E_], w_v_lo[(size_t)KVE_ * E_];
__device__ __nv_bfloat16 w_o_hi[(size_t)E_ * E_],   w_o_lo[(size_t)E_ * E_];
__device__ __nv_bfloat16 q_hi[(size_t)MR_ * E_],   q_lo[(size_t)MR_ * E_];
__device__ __nv_bfloat16 k_hi[(size_t)MR_ * KVE_], k_lo[(size_t)MR_ * KVE_];
__device__ __half        v_f16[(size_t)MR_ * KVE_];
__device__ __nv_bfloat16 a_hi[(size_t)MR_ * E_],   a_lo[(size_t)MR_ * E_];

// ================= helpers =================
__device__ __forceinline__ uint32_t smem_u32(const void* p) {
    uint32_t a;
    asm("{ .reg .u64 t; cvta.to.shared.u64 t, %1; cvt.u32.u64 %0, t; }" : "=r"(a) : "l"(p));
    return a;
}
__device__ __forceinline__ void cp16(uint32_t saddr, const void* g) {
    asm volatile("cp.async.cg.shared.global [%0], [%1], 16;" :: "r"(saddr), "l"(g));
}
#define CP_COMMIT() asm volatile("cp.async.commit_group;" ::: "memory")
#define CP_WAIT(n)  asm volatile("cp.async.wait_group %0;" :: "n"(n) : "memory")

__device__ __forceinline__ void ldm_x4(uint32_t* r, uint32_t addr) {
    asm volatile("ldmatrix.sync.aligned.m8n8.x4.shared.b16 {%0,%1,%2,%3}, [%4];"
                 : "=r"(r[0]), "=r"(r[1]), "=r"(r[2]), "=r"(r[3]) : "r"(addr));
}
__device__ __forceinline__ void ldm_x4_t(uint32_t* r, uint32_t addr) {
    asm volatile("ldmatrix.sync.aligned.m8n8.x4.trans.shared.b16 {%0,%1,%2,%3}, [%4];"
                 : "=r"(r[0]), "=r"(r[1]), "=r"(r[2]), "=r"(r[3]) : "r"(addr));
}
__device__ __forceinline__ void mma_bf16(float* d, const uint32_t* a,
                                         uint32_t b0, uint32_t b1) {
    asm volatile(
        "mma.sync.aligned.m16n8k16.row.col.f32.bf16.bf16.f32 "
        "{%0,%1,%2,%3}, {%4,%5,%6,%7}, {%8,%9}, {%0,%1,%2,%3};"
        : "+f"(d[0]), "+f"(d[1]), "+f"(d[2]), "+f"(d[3])
        : "r"(a[0]), "r"(a[1]), "r"(a[2]), "r"(a[3]), "r"(b0), "r"(b1));
}
__device__ __forceinline__ void mma_f16(float* d, const uint32_t* a,
                                        uint32_t b0, uint32_t b1) {
    asm volatile(
        "mma.sync.aligned.m16n8k16.row.col.f32.f16.f16.f32 "
        "{%0,%1,%2,%3}, {%4,%5,%6,%7}, {%8,%9}, {%0,%1,%2,%3};"
        : "+f"(d[0]), "+f"(d[1]), "+f"(d[2]), "+f"(d[3])
        : "r"(a[0]), "r"(a[1]), "r"(a[2]), "r"(a[3]), "r"(b0), "r"(b1));
}
__device__ __forceinline__ void split_store2(__nv_bfloat16* hi, __nv_bfloat16* lo,
                                             size_t off, float y0, float y1) {
    __nv_bfloat16 h0 = __float2bfloat16(y0);
    __nv_bfloat16 h1 = __float2bfloat16(y1);
    __nv_bfloat16 l0 = __float2bfloat16(y0 - __bfloat162float(h0));
    __nv_bfloat16 l1 = __float2bfloat16(y1 - __bfloat162float(h1));
    *(__nv_bfloat162*)(hi + off) = __halves2bfloat162(h0, h1);
    *(__nv_bfloat162*)(lo + off) = __halves2bfloat162(l0, l1);
}

// ================= fused split: fp32 -> bf16 hi/lo (7 segments) =================
struct SplitSegs {
    const float* x[7];
    __nv_bfloat16* hi[7];
    __nv_bfloat16* lo[7];
    int blk_end[7];    // prefix sums of blocks
};

__global__ void split_fused(SplitSegs segs)
{
    int bid = blockIdx.x;
    int seg = 0;
    int base = 0;
#pragma unroll
    for (int s = 0; s < 7; s++) {
        if (bid >= segs.blk_end[s]) { seg = s + 1; base = segs.blk_end[s]; }
    }
    int i = (bid - base) * 256 + threadIdx.x;
    const float* x = segs.x[seg];
    float4 v = ((const float4*)x)[i];
    __nv_bfloat16 h0 = __float2bfloat16(v.x);
    __nv_bfloat16 h1 = __float2bfloat16(v.y);
    __nv_bfloat16 h2 = __float2bfloat16(v.z);
    __nv_bfloat16 h3 = __float2bfloat16(v.w);
    __nv_bfloat16 l0 = __float2bfloat16(v.x - __bfloat162float(h0));
    __nv_bfloat16 l1 = __float2bfloat16(v.y - __bfloat162float(h1));
    __nv_bfloat16 l2 = __float2bfloat16(v.z - __bfloat162float(h2));
    __nv_bfloat16 l3 = __float2bfloat16(v.w - __bfloat162float(h3));
    __nv_bfloat16* hi = segs.hi[seg];
    __nv_bfloat16* lo = segs.lo[seg];
    ((__nv_bfloat162*)hi)[i * 2]     = __halves2bfloat162(h0, h1);
    ((__nv_bfloat162*)hi)[i * 2 + 1] = __halves2bfloat162(h2, h3);
    ((__nv_bfloat162*)lo)[i * 2]     = __halves2bfloat162(l0, l1);
    ((__nv_bfloat162*)lo)[i * 2 + 1] = __halves2bfloat162(l2, l3);
}

// ================= HMMA NT GEMM core =================
#define BM 128
#define BN 128
#define BK 32
#define LDSB 80
#define TILE_B (128 * LDSB)
#define STAGE_B (4 * TILE_B)
#define GSMEM (2 * STAGE_B)    // 81920

__device__ __forceinline__ void load_chunk(uint32_t sb, int stage,
    const __nv_bfloat16* __restrict__ Ah, const __nv_bfloat16* __restrict__ Al,
    const __nv_bfloat16* __restrict__ Bh, const __nv_bfloat16* __restrict__ Bl,
    int K, int tid)
{
    const __nv_bfloat16* srcs[4] = { Ah, Al, Bh, Bl };
    uint32_t base = sb + stage * STAGE_B;
#pragma unroll
    for (int t = 0; t < 4; t++) {
#pragma unroll
        for (int it = 0; it < 2; it++) {
            int idx = tid + it * 256;
            int r = idx >> 2;
            int c = idx & 3;
            cp16(base + t * TILE_B + r * LDSB + c * 16,
                 srcs[t] + (size_t)r * K + c * 8);
        }
    }
}

// mainloop: accumulates 3-term split-bf16 product into acc
__device__ __forceinline__ void gemm_mainloop(
    uint32_t sb, const __nv_bfloat16* pAh, const __nv_bfloat16* pAl,
    const __nv_bfloat16* pBh, const __nv_bfloat16* pBl,
    int K, int tid, int lane, int wm, int wn, float acc[4][4][4])
{
    const uint32_t a_off = (uint32_t)((lane & 15) * LDSB + (lane >> 4) * 16);
    const uint32_t b_off = (uint32_t)(((lane & 7) + (lane >> 4) * 8) * LDSB
                                      + ((lane >> 3) & 1) * 16);
    const int nch = K >> 5;
    load_chunk(sb, 0, pAh, pAl, pBh, pBl, K, tid);
    CP_COMMIT();

    for (int c = 0; c < nch; c++) {
        const int st = c & 1;
        if (c + 1 < nch) {
            const size_t kb = (size_t)(c + 1) * BK;
            load_chunk(sb, st ^ 1, pAh + kb, pAl + kb, pBh + kb, pBl + kb, K, tid);
            CP_COMMIT();
            CP_WAIT(1);
        } else {
            CP_WAIT(0);
        }
        __syncthreads();

        const uint32_t stb = sb + st * STAGE_B;
        const uint32_t Ah_b = stb + 0 * TILE_B;
        const uint32_t Al_b = stb + 1 * TILE_B;
        const uint32_t Bh_b = stb + 2 * TILE_B;
        const uint32_t Bl_b = stb + 3 * TILE_B;

#pragma unroll
        for (int ks = 0; ks < 2; ks++) {
            const uint32_t kbyte = ks * 32;
            uint32_t aH[4][4], bH[2][4], bL[2][4];
#pragma unroll
            for (int mi = 0; mi < 4; mi++)
                ldm_x4(aH[mi], Ah_b + (wm * 64 + mi * 16) * LDSB + kbyte + a_off);
#pragma unroll
            for (int nb = 0; nb < 2; nb++) {
                ldm_x4(bH[nb], Bh_b + (wn * 32 + nb * 16) * LDSB + kbyte + b_off);
                ldm_x4(bL[nb], Bl_b + (wn * 32 + nb * 16) * LDSB + kbyte + b_off);
            }
#pragma unroll
            for (int mi = 0; mi < 4; mi++)
#pragma unroll
                for (int ni = 0; ni < 4; ni++) {
                    mma_bf16(acc[mi][ni], aH[mi], bH[ni >> 1][(ni & 1) * 2],
                                                   bH[ni >> 1][(ni & 1) * 2 + 1]);
                    mma_bf16(acc[mi][ni], aH[mi], bL[ni >> 1][(ni & 1) * 2],
                                                   bL[ni >> 1][(ni & 1) * 2 + 1]);
                }
            uint32_t aL[4][4];
#pragma unroll
            for (int mi = 0; mi < 4; mi++)
                ldm_x4(aL[mi], Al_b + (wm * 64 + mi * 16) * LDSB + kbyte + a_off);
#pragma unroll
            for (int mi = 0; mi < 4; mi++)
#pragma unroll
                for (int ni = 0; ni < 4; ni++)
                    mma_bf16(acc[mi][ni], aL[mi], bH[ni >> 1][(ni & 1) * 2],
                                                   bH[ni >> 1][(ni & 1) * 2 + 1]);
        }
        __syncthreads();
    }
}

// ---- fused Q/K/V projection GEMM (one launch) ----
// blocks [0,512): Q, [512,640): K, [640,768): V
__global__ void __launch_bounds__(256, 2) gemm_qkv(
    const __nv_bfloat16* __restrict__ sqh, const __nv_bfloat16* __restrict__ sql,
    const __nv_bfloat16* __restrict__ wqh, const __nv_bfloat16* __restrict__ wql,
    const float* __restrict__ bq,
    __nv_bfloat16* __restrict__ qhp, __nv_bfloat16* __restrict__ qlp,
    const __nv_bfloat16* __restrict__ skh, const __nv_bfloat16* __restrict__ skl,
    const __nv_bfloat16* __restrict__ wkh, const __nv_bfloat16* __restrict__ wkl,
    const float* __restrict__ bk,
    __nv_bfloat16* __restrict__ khp, __nv_bfloat16* __restrict__ klp,
    const __nv_bfloat16* __restrict__ svh, const __nv_bfloat16* __restrict__ svl,
    const __nv_bfloat16* __restrict__ wvh, const __nv_bfloat16* __restrict__ wvl,
    const float* __restrict__ bv,
    __half* __restrict__ vfp,
    float qscale)
{
    extern __shared__ char smem[];
    const uint32_t sb = smem_u32(smem);
    const int tid = threadIdx.x;
    const int lane = tid & 31;
    const int wid = tid >> 5;
    const int wm = wid & 1;
    const int wn = wid >> 1;

    const int bid = blockIdx.x;
    const int seg = (bid < 512) ? 0 : (bid < 640 ? 1 : 2);
    const int local = bid - (seg == 0 ? 0 : (seg == 1 ? 512 : 640));
    const int tilesX = (seg == 0) ? (E_ / BN) : (KVE_ / BN);
    const int m0 = (local / tilesX) * BM;
    const int n0 = (local % tilesX) * BN;

    const __nv_bfloat16* Ah = (seg == 0) ? sqh : (seg == 1 ? skh : svh);
    const __nv_bfloat16* Al = (seg == 0) ? sql : (seg == 1 ? skl : svl);
    const __nv_bfloat16* Bh = (seg == 0) ? wqh : (seg == 1 ? wkh : wvh);
    const __nv_bfloat16* Bl = (seg == 0) ? wql : (seg == 1 ? wkl : wvl);
    const float* bias = (seg == 0) ? bq : (seg == 1 ? bk : bv);
    const int Nn = (seg == 0) ? E_ : KVE_;
    const float scale = (seg == 0) ? qscale : 1.f;

    float acc[4][4][4];
#pragma unroll
    for (int i = 0; i < 4; i++)
#pragma unroll
        for (int j = 0; j < 4; j++)
#pragma unroll
            for (int q = 0; q < 4; q++) acc[i][j][q] = 0.f;

    gemm_mainloop(sb, Ah + (size_t)m0 * E_, Al + (size_t)m0 * E_,
                  Bh + (size_t)n0 * E_, Bl + (size_t)n0 * E_,
                  E_, tid, lane, wm, wn, acc);

    // ---- epilogue ----
    const int g = lane >> 2;
    const int cq = lane & 3;
#pragma unroll
    for (int mi = 0; mi < 4; mi++) {
#pragma unroll
        for (int ni = 0; ni < 4; ni++) {
            const int col = n0 + wn * 32 + ni * 8 + cq * 2;
            const float b0 = bias[col];
            const float b1 = bias[col + 1];
#pragma unroll
            for (int h = 0; h < 2; h++) {
                const int row = m0 + wm * 64 + mi * 16 + g + h * 8;
                const float y0 = (acc[mi][ni][h * 2 + 0] + b0) * scale;
                const float y1 = (acc[mi][ni][h * 2 + 1] + b1) * scale;
                const size_t off = (size_t)row * Nn + col;
                if (seg == 0)      split_store2(qhp, qlp, off, y0, y1);
                else if (seg == 1) split_store2(khp, klp, off, y0, y1);
                else               *(__half2*)(vfp + off) = __floats2half2_rn(y0, y1);
            }
        }
    }
}

// ---- O projection GEMM (fp32 out) ----
__global__ void __launch_bounds__(256, 2) gemm_o(
    const __nv_bfloat16* __restrict__ Ahi, const __nv_bfloat16* __restrict__ Alo,
    const __nv_bfloat16* __restrict__ Bhi, const __nv_bfloat16* __restrict__ Blo,
    const float* __restrict__ bias, float* __restrict__ C)
{
    extern __shared__ char smem[];
    const uint32_t sb = smem_u32(smem);
    const int tid = threadIdx.x;
    const int lane = tid & 31;
    const int wid = tid >> 5;
    const int wm = wid & 1;
    const int wn = wid >> 1;
    const int m0 = blockIdx.y * BM;
    const int n0 = blockIdx.x * BN;

    float acc[4][4][4];
#pragma unroll
    for (int i = 0; i < 4; i++)
#pragma unroll
        for (int j = 0; j < 4; j++)
#pragma unroll
            for (int q = 0; q < 4; q++) acc[i][j][q] = 0.f;

    gemm_mainloop(sb, Ahi + (size_t)m0 * E_, Alo + (size_t)m0 * E_,
                  Bhi + (size_t)n0 * E_, Blo + (size_t)n0 * E_,
                  E_, tid, lane, wm, wn, acc);

    const int g = lane >> 2;
    const int cq = lane & 3;
#pragma unroll
    for (int mi = 0; mi < 4; mi++) {
#pragma unroll
        for (int ni = 0; ni < 4; ni++) {
            const int col = n0 + wn * 32 + ni * 8 + cq * 2;
            const float b0 = bias[col];
            const float b1 = bias[col + 1];
#pragma unroll
            for (int h = 0; h < 2; h++) {
                const int row = m0 + wm * 64 + mi * 16 + g + h * 8;
                float2 v;
                v.x = acc[mi][ni][h * 2 + 0] + b0;
                v.y = acc[mi][ni][h * 2 + 1] + b1;
                *(float2*)(C + (size_t)row * E_ + col) = v;
            }
        }
    }
}

// =================================================================
// HMMA flash attention (unchanged core; qt reversed for load balance)
// =================================================================
#define QSTR 272
#define AT_QH   0
#define AT_QL   (128 * QSTR)
#define AT_KV0  (2 * 128 * QSTR)
#define AT_STG  (3 * 64 * QSTR)
#define AT_KH   0
#define AT_KL   (64 * QSTR)
#define AT_VV   (2 * 64 * QSTR)
#define AT_SMEM (AT_KV0 + 2 * AT_STG)  // 174080

__device__ __forceinline__ void attn_load_kv(uint32_t sb, int stage, int b, int hk,
                                             int kt, const __nv_bfloat16* kh,
                                             const __nv_bfloat16* kl,
                                             const __half* vv, int tid)
{
    const uint32_t base = sb + AT_KV0 + stage * AT_STG;
    const size_t rowg = (size_t)(b * N_ + kt * 64);
#pragma unroll
    for (int it = 0; it < 12; it++) {
        int idx = tid + it * 256;
        int buf = idx >> 10;
        int r = (idx & 1023) >> 4;
        int c = idx & 15;
        uint32_t dst = base + (buf == 0 ? AT_KH : (buf == 1 ? AT_KL : AT_VV))
                     + r * QSTR + c * 16;
        if (buf == 0)
            cp16(dst, kh + (rowg + r) * KVE_ + hk * D_ + c * 8);
        else if (buf == 1)
            cp16(dst, kl + (rowg + r) * KVE_ + hk * D_ + c * 8);
        else
            cp16(dst, vv + (rowg + r) * KVE_ + hk * D_ + c * 8);
    }
}

__global__ void __launch_bounds__(256, 1) attn_mma(
    const __nv_bfloat16* __restrict__ qh, const __nv_bfloat16* __restrict__ ql,
    const __nv_bfloat16* __restrict__ kh, const __nv_bfloat16* __restrict__ kl,
    const __half* __restrict__ vv,
    __nv_bfloat16* __restrict__ ah, __nv_bfloat16* __restrict__ al,
    const int* __restrict__ causal_p)
{
    extern __shared__ char smem[];
    const uint32_t sb = smem_u32(smem);
    const int tid = threadIdx.x;
    const int lane = tid & 31;
    const int wid = tid >> 5;
    const int qt = (int)(gridDim.x - 1 - blockIdx.x);  // heavy tiles first
    const int bh = blockIdx.y;
    const int b  = bh >> 4;
    const int hq = bh & 15;
    const int hk = hq >> 2;
    const int wr = wid * 16;
    const int g = lane >> 2;
    const int cq = lane & 3;
    const bool causal = (causal_p[0] != 0);

    const uint32_t a_off = (uint32_t)((lane & 15) * QSTR + (lane >> 4) * 16);
    const uint32_t b_off = (uint32_t)(((lane & 7) + (lane >> 4) * 8) * QSTR
                                      + ((lane >> 3) & 1) * 16);

    {
        const size_t rowg = (size_t)(b * N_ + qt * 128);
#pragma unroll
        for (int it = 0; it < 16; it++) {
            int idx = tid + it * 256;
            int buf = idx >> 11;
            int r = (idx & 2047) >> 4;
            int c = idx & 15;
            uint32_t dst = sb + (buf ? AT_QL : AT_QH) + r * QSTR + c * 16;
            const __nv_bfloat16* src = buf ? ql : qh;
            cp16(dst, src + (rowg + r) * E_ + hq * D_ + c * 8);
        }
    }
    attn_load_kv(sb, 0, b, hk, 0, kh, kl, vv, tid);
    CP_COMMIT();

    float m_i[2] = { -1e30f, -1e30f };
    float l_i[2] = { 0.f, 0.f };
    float o[16][4];
#pragma unroll
    for (int i = 0; i < 16; i++)
#pragma unroll
        for (int j = 0; j < 4; j++) o[i][j] = 0.f;

    const int ktend = causal ? 2 * (qt + 1) : (N_ / 64);

    for (int kt = 0; kt < ktend; kt++) {
        const int st = kt & 1;
        if (kt + 1 < ktend) {
            attn_load_kv(sb, st ^ 1, b, hk, kt + 1, kh, kl, vv, tid);
            CP_COMMIT();
            CP_WAIT(1);
        } else {
            CP_WAIT(0);
        }
        __syncthreads();

        const uint32_t KHb = sb + AT_KV0 + st * AT_STG + AT_KH;
        const uint32_t KLb = sb + AT_KV0 + st * AT_STG + AT_KL;
        const uint32_t VVb = sb + AT_KV0 + st * AT_STG + AT_VV;

        float s[8][4];
#pragma unroll
        for (int i = 0; i < 8; i++)
#pragma unroll
            for (int j = 0; j < 4; j++) s[i][j] = 0.f;

#pragma unroll
        for (int ks = 0; ks < 8; ks++) {
            const uint32_t kb = ks * 32;
            uint32_t aH[4], aL[4];
            ldm_x4(aH, sb + AT_QH + wr * QSTR + kb + a_off);
            ldm_x4(aL, sb + AT_QL + wr * QSTR + kb + a_off);
#pragma unroll
            for (int t = 0; t < 4; t++) {
                uint32_t bh4[4], bl4[4];
                ldm_x4(bh4, KHb + (t * 16) * QSTR + kb + b_off);
                ldm_x4(bl4, KLb + (t * 16) * QSTR + kb + b_off);
                mma_bf16(s[2 * t],     aH, bh4[0], bh4[1]);
                mma_bf16(s[2 * t],     aH, bl4[0], bl4[1]);
                mma_bf16(s[2 * t],     aL, bh4[0], bh4[1]);
                mma_bf16(s[2 * t + 1], aH, bh4[2], bh4[3]);
                mma_bf16(s[2 * t + 1], aH, bl4[2], bl4[3]);
                mma_bf16(s[2 * t + 1], aL, bh4[2], bh4[3]);
            }
        }

        const int row0 = qt * 128 + wr + g;
        if (causal && (kt * 64 + 63 > qt * 128 + wr)) {
            const int col0 = kt * 64 + 2 * cq;
#pragma unroll
            for (int ni = 0; ni < 8; ni++)
#pragma unroll
                for (int j = 0; j < 4; j++) {
                    int row = row0 + (j >> 1) * 8;
                    int col = col0 + ni * 8 + (j & 1);
                    if (col > row) s[ni][j] = -1e30f;
                }
        }

#pragma unroll
        for (int h = 0; h < 2; h++) {
            float rm = -1e30f;
#pragma unroll
            for (int ni = 0; ni < 8; ni++)
                rm = fmaxf(rm, fmaxf(s[ni][2 * h], s[ni][2 * h + 1]));
            rm = fmaxf(rm, __shfl_xor_sync(0xffffffffu, rm, 1));
            rm = fmaxf(rm, __shfl_xor_sync(0xffffffffu, rm, 2));
            const float mn = fmaxf(m_i[h], rm);
            const float alpha = __expf(m_i[h] - mn);
            m_i[h] = mn;
            float rs = 0.f;
#pragma unroll
            for (int ni = 0; ni < 8; ni++) {
                float e0 = __expf(s[ni][2 * h]     - mn);
                float e1 = __expf(s[ni][2 * h + 1] - mn);
                s[ni][2 * h] = e0; s[ni][2 * h + 1] = e1;
                rs += e0 + e1;
            }
            rs += __shfl_xor_sync(0xffffffffu, rs, 1);
            rs += __shfl_xor_sync(0xffffffffu, rs, 2);
            l_i[h] = l_i[h] * alpha + rs;
#pragma unroll
            for (int np = 0; np < 16; np++) {
                o[np][2 * h]     *= alpha;
                o[np][2 * h + 1] *= alpha;
            }
        }

#pragma unroll
        for (int ks = 0; ks < 4; ks++) {
            uint32_t aPh[4], aPl[4];
#pragma unroll
            for (int q = 0; q < 4; q++) {
                const int ni = 2 * ks + (q >> 1);
                const int j0 = (q & 1) * 2;
                float e0 = s[ni][j0], e1 = s[ni][j0 + 1];
                __half2 hh = __floats2half2_rn(e0, e1);
                aPh[q] = *(uint32_t*)&hh;
                float2 hf = __half22float2(hh);
                __half2 ll = __floats2half2_rn(e0 - hf.x, e1 - hf.y);
                aPl[q] = *(uint32_t*)&ll;
            }
#pragma unroll
            for (int np = 0; np < 8; np++) {
                uint32_t bv[4];
                ldm_x4_t(bv, VVb + (ks * 16) * QSTR + np * 32 + a_off);
                mma_f16(o[2 * np],     aPh, bv[0], bv[1]);
                mma_f16(o[2 * np],     aPl, bv[0], bv[1]);
                mma_f16(o[2 * np + 1], aPh, bv[2], bv[3]);
                mma_f16(o[2 * np + 1], aPl, bv[2], bv[3]);
            }
        }
        __syncthreads();
    }

    const float inv0 = 1.f / l_i[0];
    const float inv1 = 1.f / l_i[1];
    const size_t rowa = (size_t)(b * N_ + qt * 128 + wr + g);
    const int colb = hq * D_ + 2 * cq;
#pragma unroll
    for (int np = 0; np < 16; np++) {
        const size_t off0 = rowa * E_ + colb + np * 8;
        split_store2(ah, al, off0, o[np][0] * inv0, o[np][1] * inv0);
        const size_t off1 = (rowa + 8) * E_ + colb + np * 8;
        split_store2(ah, al, off1, o[np][2] * inv1, o[np][3] * inv1);
    }
}

// =================================================================
extern "C" void kernel_launch(void* const* d_in, const int* in_sizes, int n_in,
                              void* d_out, int out_size)
{
    const float* query = (const float*)d_in[0];
    const float* key   = (const float*)d_in[1];
    const float* value = (const float*)d_in[2];
    const float* Wq = (const float*)d_in[3];
    const float* bq = (const float*)d_in[4];
    const float* Wk = (const float*)d_in[5];
    const float* bk = (const float*)d_in[6];
    const float* Wv = (const float*)d_in[7];
    const float* bv = (const float*)d_in[8];
    const float* Wo = (const float*)d_in[9];
    const float* bo = (const float*)d_in[10];
    const int* is_causal = (const int*)d_in[11];
    float* out = (float*)d_out;

    __nv_bfloat16 *sqh, *sql, *skh, *skl, *svh, *svl;
    __nv_bfloat16 *wqh, *wql, *wkh, *wkl, *wvh, *wvl, *woh, *wol;
    __nv_bfloat16 *qhp, *qlp, *khp, *klp, *ahp, *alp;
    __half *vfp;
    cudaGetSymbolAddress((void**)&sqh, s_q_hi);  cudaGetSymbolAddress((void**)&sql, s_q_lo);
    cudaGetSymbolAddress((void**)&skh, s_k_hi);  cudaGetSymbolAddress((void**)&skl, s_k_lo);
    cudaGetSymbolAddress((void**)&svh, s_v_hi);  cudaGetSymbolAddress((void**)&svl, s_v_lo);
    cudaGetSymbolAddress((void**)&wqh, w_q_hi);  cudaGetSymbolAddress((void**)&wql, w_q_lo);
    cudaGetSymbolAddress((void**)&wkh, w_k_hi);  cudaGetSymbolAddress((void**)&wkl, w_k_lo);
    cudaGetSymbolAddress((void**)&wvh, w_v_hi);  cudaGetSymbolAddress((void**)&wvl, w_v_lo);
    cudaGetSymbolAddress((void**)&woh, w_o_hi);  cudaGetSymbolAddress((void**)&wol, w_o_lo);
    cudaGetSymbolAddress((void**)&qhp, q_hi);    cudaGetSymbolAddress((void**)&qlp, q_lo);
    cudaGetSymbolAddress((void**)&khp, k_hi);    cudaGetSymbolAddress((void**)&klp, k_lo);
    cudaGetSymbolAddress((void**)&vfp, v_f16);
    cudaGetSymbolAddress((void**)&ahp, a_hi);    cudaGetSymbolAddress((void**)&alp, a_lo);

    const float qscale = 0.08838834764831845f;  // 1/sqrt(128)

    // ---- fused input splits (7 segments, one launch) ----
    const int actN4 = (MR_ * E_) / 4;   // 2,097,152 -> 8192 blocks
    const int wqN4  = (E_ * E_) / 4;    // 4096 blocks
    const int wkN4  = (KVE_ * E_) / 4;  // 1024 blocks
    SplitSegs segs;
    segs.x[0] = query; segs.hi[0] = sqh; segs.lo[0] = sql;
    segs.x[1] = key;   segs.hi[1] = skh; segs.lo[1] = skl;
    segs.x[2] = value; segs.hi[2] = svh; segs.lo[2] = svl;
    segs.x[3] = Wq;    segs.hi[3] = wqh; segs.lo[3] = wql;
    segs.x[4] = Wk;    segs.hi[4] = wkh; segs.lo[4] = wkl;
    segs.x[5] = Wv;    segs.hi[5] = wvh; segs.lo[5] = wvl;
    segs.x[6] = Wo;    segs.hi[6] = woh; segs.lo[6] = wol;
    int nb = 0;
    const int segBlocks[7] = { actN4/256, actN4/256, actN4/256,
                               wqN4/256, wkN4/256, wkN4/256, wqN4/256 };
    for (int s = 0; s < 7; s++) { nb += segBlocks[s]; segs.blk_end[s] = nb; }
    split_fused<<<nb, 256>>>(segs);

    // ---- fused Q/K/V projection GEMMs ----
    cudaFuncSetAttribute(gemm_qkv, cudaFuncAttributeMaxDynamicSharedMemorySize, GSMEM);
    cudaFuncSetAttribute(gemm_o,   cudaFuncAttributeMaxDynamicSharedMemorySize, GSMEM);
    const int qkvBlocks = (E_ / BN) * (MR_ / BM) + 2 * (KVE_ / BN) * (MR_ / BM); // 768
    gemm_qkv<<<qkvBlocks, 256, GSMEM>>>(
        sqh, sql, wqh, wql, bq, qhp, qlp,
        skh, skl, wkh, wkl, bk, khp, klp,
        svh, svl, wvh, wvl, bv, vfp, qscale);

    // ---- HMMA flash attention (heavy tiles first) ----
    cudaFuncSetAttribute(attn_mma, cudaFuncAttributeMaxDynamicSharedMemorySize, AT_SMEM);
    attn_mma<<<dim3(N_ / 128, B_ * HQ_), 256, AT_SMEM>>>(
        qhp, qlp, khp, klp, vfp, ahp, alp, is_causal);

    // ---- O projection (fp32 out) ----
    gemm_o<<<dim3(E_ / BN, MR_ / BM), 256, GSMEM>>>(ahp, alp, woh, wol, bo, out);
}

// round 7
// speedup vs baseline: 4.6015x; 1.3441x over previous
#include <cuda_runtime.h>
#include <cuda_bf16.h>
#include <cuda_fp16.h>
#include <cstdint>
#include <math.h>

#define E_    2048
#define HQ_   16
#define HK_   4
#define D_    128
#define KVE_  512
#define B_    2
#define N_    2048
#define MR_   (B_ * N_)   // 4096 rows

// ---------------- scratch (no allocations allowed) ----------------
// activation splits (fp16 hi/lo) = GEMM A operands
__device__ __half s_q_hi[(size_t)MR_ * E_],  s_q_lo[(size_t)MR_ * E_];
__device__ __half s_k_hi[(size_t)MR_ * E_],  s_k_lo[(size_t)MR_ * E_];
__device__ __half s_v_hi[(size_t)MR_ * E_],  s_v_lo[(size_t)MR_ * E_];
// weights: single fp16
__device__ __half w_q[(size_t)E_ * E_];
__device__ __half w_k[(size_t)KVE_ * E_];
__device__ __half w_v[(size_t)KVE_ * E_];
__device__ __half w_o[(size_t)E_ * E_];
// projection outputs
__device__ __half q_h16[(size_t)MR_ * E_], q_l16[(size_t)MR_ * E_];  // q split (unscaled)
__device__ __half k_f16[(size_t)MR_ * KVE_];
__device__ __half v_f16[(size_t)MR_ * KVE_];
// attention output (fp16 hi/lo = O-proj A operand)
__device__ __half a_h16[(size_t)MR_ * E_], a_l16[(size_t)MR_ * E_];

// ================= helpers =================
__device__ __forceinline__ uint32_t smem_u32(const void* p) {
    uint32_t a;
    asm("{ .reg .u64 t; cvta.to.shared.u64 t, %1; cvt.u32.u64 %0, t; }" : "=r"(a) : "l"(p));
    return a;
}
__device__ __forceinline__ void cp16(uint32_t saddr, const void* g) {
    asm volatile("cp.async.cg.shared.global [%0], [%1], 16;" :: "r"(saddr), "l"(g));
}
#define CP_COMMIT() asm volatile("cp.async.commit_group;" ::: "memory")
#define CP_WAIT(n)  asm volatile("cp.async.wait_group %0;" :: "n"(n) : "memory")

__device__ __forceinline__ void ldm_x4(uint32_t* r, uint32_t addr) {
    asm volatile("ldmatrix.sync.aligned.m8n8.x4.shared.b16 {%0,%1,%2,%3}, [%4];"
                 : "=r"(r[0]), "=r"(r[1]), "=r"(r[2]), "=r"(r[3]) : "r"(addr));
}
__device__ __forceinline__ void ldm_x4_t(uint32_t* r, uint32_t addr) {
    asm volatile("ldmatrix.sync.aligned.m8n8.x4.trans.shared.b16 {%0,%1,%2,%3}, [%4];"
                 : "=r"(r[0]), "=r"(r[1]), "=r"(r[2]), "=r"(r[3]) : "r"(addr));
}
__device__ __forceinline__ void mma_f16(float* d, const uint32_t* a,
                                        uint32_t b0, uint32_t b1) {
    asm volatile(
        "mma.sync.aligned.m16n8k16.row.col.f32.f16.f16.f32 "
        "{%0,%1,%2,%3}, {%4,%5,%6,%7}, {%8,%9}, {%0,%1,%2,%3};"
        : "+f"(d[0]), "+f"(d[1]), "+f"(d[2]), "+f"(d[3])
        : "r"(a[0]), "r"(a[1]), "r"(a[2]), "r"(a[3]), "r"(b0), "r"(b1));
}
__device__ __forceinline__ void split_store2h(__half* hi, __half* lo,
                                              size_t off, float y0, float y1) {
    __half h0 = __float2half(y0);
    __half h1 = __float2half(y1);
    __half l0 = __float2half(y0 - __half2float(h0));
    __half l1 = __float2half(y1 - __half2float(h1));
    *(__half2*)(hi + off) = __halves2half2(h0, h1);
    *(__half2*)(lo + off) = __halves2half2(l0, l1);
}

// ========== fused convert: fp32 -> fp16 hi(/lo) over 7 segments ==========
struct SplitSegs {
    const float* x[7];
    __half* hi[7];
    __half* lo[7];      // nullptr -> single-precision convert only
    int blk_end[7];
};

__global__ void split_fused(SplitSegs segs)
{
    int bid = blockIdx.x;
    int seg = 0;
    int base = 0;
#pragma unroll
    for (int s = 0; s < 7; s++) {
        if (bid >= segs.blk_end[s]) { seg = s + 1; base = segs.blk_end[s]; }
    }
    int i = (bid - base) * 256 + threadIdx.x;
    float4 v = ((const float4*)segs.x[seg])[i];
    __half h0 = __float2half(v.x);
    __half h1 = __float2half(v.y);
    __half h2 = __float2half(v.z);
    __half h3 = __float2half(v.w);
    __half* hi = segs.hi[seg];
    ((__half2*)hi)[i * 2]     = __halves2half2(h0, h1);
    ((__half2*)hi)[i * 2 + 1] = __halves2half2(h2, h3);
    __half* lo = segs.lo[seg];
    if (lo) {
        __half l0 = __float2half(v.x - __half2float(h0));
        __half l1 = __float2half(v.y - __half2float(h1));
        __half l2 = __float2half(v.z - __half2float(h2));
        __half l3 = __float2half(v.w - __half2float(h3));
        ((__half2*)lo)[i * 2]     = __halves2half2(l0, l1);
        ((__half2*)lo)[i * 2 + 1] = __halves2half2(l2, l3);
    }
}

// ================= HMMA NT GEMM core (fp16, A-split 2-term) =================
#define BM 128
#define BN 128
#define BK 32
#define LDSB 80
#define TILE_B (128 * LDSB)      // 10240
#define STAGE_B (3 * TILE_B)     // Ah, Al, B
#define GSMEM (2 * STAGE_B)      // 61440

__device__ __forceinline__ void load_chunk(uint32_t sb, int stage,
    const __half* __restrict__ Ah, const __half* __restrict__ Al,
    const __half* __restrict__ Bw, int K, int tid)
{
    const __half* srcs[3] = { Ah, Al, Bw };
    uint32_t base = sb + stage * STAGE_B;
#pragma unroll
    for (int t = 0; t < 3; t++) {
#pragma unroll
        for (int it = 0; it < 2; it++) {
            int idx = tid + it * 256;
            int r = idx >> 2;
            int c = idx & 3;
            cp16(base + t * TILE_B + r * LDSB + c * 16,
                 srcs[t] + (size_t)r * K + c * 8);
        }
    }
}

__device__ __forceinline__ void gemm_mainloop(
    uint32_t sb, const __half* pAh, const __half* pAl, const __half* pB,
    int K, int tid, int lane, int wm, int wn, float acc[4][4][4])
{
    const uint32_t a_off = (uint32_t)((lane & 15) * LDSB + (lane >> 4) * 16);
    const uint32_t b_off = (uint32_t)(((lane & 7) + (lane >> 4) * 8) * LDSB
                                      + ((lane >> 3) & 1) * 16);
    const int nch = K >> 5;
    load_chunk(sb, 0, pAh, pAl, pB, K, tid);
    CP_COMMIT();

    for (int c = 0; c < nch; c++) {
        const int st = c & 1;
        if (c + 1 < nch) {
            const size_t kb = (size_t)(c + 1) * BK;
            load_chunk(sb, st ^ 1, pAh + kb, pAl + kb, pB + kb, K, tid);
            CP_COMMIT();
            CP_WAIT(1);
        } else {
            CP_WAIT(0);
        }
        __syncthreads();

        const uint32_t stb = sb + st * STAGE_B;
        const uint32_t Ah_b = stb + 0 * TILE_B;
        const uint32_t Al_b = stb + 1 * TILE_B;
        const uint32_t Bw_b = stb + 2 * TILE_B;

#pragma unroll
        for (int ks = 0; ks < 2; ks++) {
            const uint32_t kbyte = ks * 32;
            uint32_t aH[4][4], bW[2][4];
#pragma unroll
            for (int mi = 0; mi < 4; mi++)
                ldm_x4(aH[mi], Ah_b + (wm * 64 + mi * 16) * LDSB + kbyte + a_off);
#pragma unroll
            for (int nb = 0; nb < 2; nb++)
                ldm_x4(bW[nb], Bw_b + (wn * 32 + nb * 16) * LDSB + kbyte + b_off);
#pragma unroll
            for (int mi = 0; mi < 4; mi++)
#pragma unroll
                for (int ni = 0; ni < 4; ni++)
                    mma_f16(acc[mi][ni], aH[mi], bW[ni >> 1][(ni & 1) * 2],
                                                  bW[ni >> 1][(ni & 1) * 2 + 1]);
            uint32_t aL[4][4];
#pragma unroll
            for (int mi = 0; mi < 4; mi++)
                ldm_x4(aL[mi], Al_b + (wm * 64 + mi * 16) * LDSB + kbyte + a_off);
#pragma unroll
            for (int mi = 0; mi < 4; mi++)
#pragma unroll
                for (int ni = 0; ni < 4; ni++)
                    mma_f16(acc[mi][ni], aL[mi], bW[ni >> 1][(ni & 1) * 2],
                                                  bW[ni >> 1][(ni & 1) * 2 + 1]);
        }
        __syncthreads();
    }
}

// ---- fused Q/K/V projection GEMM (one launch) ----
// blocks [0,512): Q, [512,640): K, [640,768): V
__global__ void __launch_bounds__(256, 2) gemm_qkv(
    const __half* __restrict__ sqh, const __half* __restrict__ sql,
    const __half* __restrict__ wq, const float* __restrict__ bq,
    __half* __restrict__ qhp, __half* __restrict__ qlp,
    const __half* __restrict__ skh, const __half* __restrict__ skl,
    const __half* __restrict__ wk, const float* __restrict__ bk,
    __half* __restrict__ kfp,
    const __half* __restrict__ svh, const __half* __restrict__ svl,
    const __half* __restrict__ wv, const float* __restrict__ bv,
    __half* __restrict__ vfp)
{
    extern __shared__ char smem[];
    const uint32_t sb = smem_u32(smem);
    const int tid = threadIdx.x;
    const int lane = tid & 31;
    const int wid = tid >> 5;
    const int wm = wid & 1;
    const int wn = wid >> 1;

    const int bid = blockIdx.x;
    const int seg = (bid < 512) ? 0 : (bid < 640 ? 1 : 2);
    const int local = bid - (seg == 0 ? 0 : (seg == 1 ? 512 : 640));
    const int tilesX = (seg == 0) ? (E_ / BN) : (KVE_ / BN);
    const int m0 = (local / tilesX) * BM;
    const int n0 = (local % tilesX) * BN;

    const __half* Ah = (seg == 0) ? sqh : (seg == 1 ? skh : svh);
    const __half* Al = (seg == 0) ? sql : (seg == 1 ? skl : svl);
    const __half* Bw = (seg == 0) ? wq : (seg == 1 ? wk : wv);
    const float* bias = (seg == 0) ? bq : (seg == 1 ? bk : bv);
    const int Nn = (seg == 0) ? E_ : KVE_;

    float acc[4][4][4];
#pragma unroll
    for (int i = 0; i < 4; i++)
#pragma unroll
        for (int j = 0; j < 4; j++)
#pragma unroll
            for (int q = 0; q < 4; q++) acc[i][j][q] = 0.f;

    gemm_mainloop(sb, Ah + (size_t)m0 * E_, Al + (size_t)m0 * E_,
                  Bw + (size_t)n0 * E_, E_, tid, lane, wm, wn, acc);

    const int g = lane >> 2;
    const int cq = lane & 3;
#pragma unroll
    for (int mi = 0; mi < 4; mi++) {
#pragma unroll
        for (int ni = 0; ni < 4; ni++) {
            const int col = n0 + wn * 32 + ni * 8 + cq * 2;
            const float b0 = bias[col];
            const float b1 = bias[col + 1];
#pragma unroll
            for (int h = 0; h < 2; h++) {
                const int row = m0 + wm * 64 + mi * 16 + g + h * 8;
                const float y0 = acc[mi][ni][h * 2 + 0] + b0;
                const float y1 = acc[mi][ni][h * 2 + 1] + b1;
                const size_t off = (size_t)row * Nn + col;
                if (seg == 0)      split_store2h(qhp, qlp, off, y0, y1);
                else if (seg == 1) *(__half2*)(kfp + off) = __floats2half2_rn(y0, y1);
                else               *(__half2*)(vfp + off) = __floats2half2_rn(y0, y1);
            }
        }
    }
}

// ---- O projection GEMM (fp32 out) ----
__global__ void __launch_bounds__(256, 2) gemm_o(
    const __half* __restrict__ Ahi, const __half* __restrict__ Alo,
    const __half* __restrict__ Bw,
    const float* __restrict__ bias, float* __restrict__ C)
{
    extern __shared__ char smem[];
    const uint32_t sb = smem_u32(smem);
    const int tid = threadIdx.x;
    const int lane = tid & 31;
    const int wid = tid >> 5;
    const int wm = wid & 1;
    const int wn = wid >> 1;
    const int m0 = blockIdx.y * BM;
    const int n0 = blockIdx.x * BN;

    float acc[4][4][4];
#pragma unroll
    for (int i = 0; i < 4; i++)
#pragma unroll
        for (int j = 0; j < 4; j++)
#pragma unroll
            for (int q = 0; q < 4; q++) acc[i][j][q] = 0.f;

    gemm_mainloop(sb, Ahi + (size_t)m0 * E_, Alo + (size_t)m0 * E_,
                  Bw + (size_t)n0 * E_, E_, tid, lane, wm, wn, acc);

    const int g = lane >> 2;
    const int cq = lane & 3;
#pragma unroll
    for (int mi = 0; mi < 4; mi++) {
#pragma unroll
        for (int ni = 0; ni < 4; ni++) {
            const int col = n0 + wn * 32 + ni * 8 + cq * 2;
            const float b0 = bias[col];
            const float b1 = bias[col + 1];
#pragma unroll
            for (int h = 0; h < 2; h++) {
                const int row = m0 + wm * 64 + mi * 16 + g + h * 8;
                float2 v;
                v.x = acc[mi][ni][h * 2 + 0] + b0;
                v.y = acc[mi][ni][h * 2 + 1] + b1;
                *(float2*)(C + (size_t)row * E_ + col) = v;
            }
        }
    }
}

// =================================================================
// HMMA flash attention: Q split fp16 2-term, K/V single fp16.
// Logit scale (1/sqrt(D)) applied post-MMA.
// =================================================================
#define QSTR 272
#define AT_QH   0
#define AT_QL   (128 * QSTR)
#define AT_KV0  (2 * 128 * QSTR)       // 69632
#define AT_STG  (2 * 64 * QSTR)        // 34816 (K, V)
#define AT_K    0
#define AT_V    (64 * QSTR)
#define AT_SMEM (AT_KV0 + 2 * AT_STG)  // 139264

__device__ __forceinline__ void attn_load_kv(uint32_t sb, int stage, int b, int hk,
                                             int kt, const __half* kf,
                                             const __half* vf, int tid)
{
    const uint32_t base = sb + AT_KV0 + stage * AT_STG;
    const size_t rowg = (size_t)(b * N_ + kt * 64);
#pragma unroll
    for (int it = 0; it < 8; it++) {
        int idx = tid + it * 256;              // 0..2047
        int buf = idx >> 10;                   // 0: K, 1: V
        int r = (idx & 1023) >> 4;             // 0..63
        int c = idx & 15;
        uint32_t dst = base + (buf ? AT_V : AT_K) + r * QSTR + c * 16;
        const __half* src = buf ? vf : kf;
        cp16(dst, src + (rowg + r) * KVE_ + hk * D_ + c * 8);
    }
}

__global__ void __launch_bounds__(256, 1) attn_mma(
    const __half* __restrict__ qh, const __half* __restrict__ ql,
    const __half* __restrict__ kf, const __half* __restrict__ vf,
    __half* __restrict__ ah, __half* __restrict__ al,
    const int* __restrict__ causal_p)
{
    extern __shared__ char smem[];
    const uint32_t sb = smem_u32(smem);
    const int tid = threadIdx.x;
    const int lane = tid & 31;
    const int wid = tid >> 5;
    const int qt = (int)(gridDim.x - 1 - blockIdx.x);  // heavy tiles first
    const int bh = blockIdx.y;
    const int b  = bh >> 4;
    const int hq = bh & 15;
    const int hk = hq >> 2;
    const int wr = wid * 16;
    const int g = lane >> 2;
    const int cq = lane & 3;
    const bool causal = (causal_p[0] != 0);
    const float lscale = 0.08838834764831845f;  // 1/sqrt(128)

    const uint32_t a_off = (uint32_t)((lane & 15) * QSTR + (lane >> 4) * 16);
    const uint32_t b_off = (uint32_t)(((lane & 7) + (lane >> 4) * 8) * QSTR
                                      + ((lane >> 3) & 1) * 16);

    {
        const size_t rowg = (size_t)(b * N_ + qt * 128);
#pragma unroll
        for (int it = 0; it < 16; it++) {
            int idx = tid + it * 256;
            int buf = idx >> 11;
            int r = (idx & 2047) >> 4;
            int c = idx & 15;
            uint32_t dst = sb + (buf ? AT_QL : AT_QH) + r * QSTR + c * 16;
            const __half* src = buf ? ql : qh;
            cp16(dst, src + (rowg + r) * E_ + hq * D_ + c * 8);
        }
    }
    attn_load_kv(sb, 0, b, hk, 0, kf, vf, tid);
    CP_COMMIT();

    float m_i[2] = { -1e30f, -1e30f };
    float l_i[2] = { 0.f, 0.f };
    float o[16][4];
#pragma unroll
    for (int i = 0; i < 16; i++)
#pragma unroll
        for (int j = 0; j < 4; j++) o[i][j] = 0.f;

    const int ktend = causal ? 2 * (qt + 1) : (N_ / 64);

    for (int kt = 0; kt < ktend; kt++) {
        const int st = kt & 1;
        if (kt + 1 < ktend) {
            attn_load_kv(sb, st ^ 1, b, hk, kt + 1, kf, vf, tid);
            CP_COMMIT();
            CP_WAIT(1);
        } else {
            CP_WAIT(0);
        }
        __syncthreads();

        const uint32_t Kb = sb + AT_KV0 + st * AT_STG + AT_K;
        const uint32_t Vb = sb + AT_KV0 + st * AT_STG + AT_V;

        // ---- S = Q K^T (16 rows x 64 cols per warp), fp16 2-term ----
        float s[8][4];
#pragma unroll
        for (int i = 0; i < 8; i++)
#pragma unroll
            for (int j = 0; j < 4; j++) s[i][j] = 0.f;

#pragma unroll
        for (int ks = 0; ks < 8; ks++) {
            const uint32_t kb = ks * 32;
            uint32_t aH[4], aL[4];
            ldm_x4(aH, sb + AT_QH + wr * QSTR + kb + a_off);
            ldm_x4(aL, sb + AT_QL + wr * QSTR + kb + a_off);
#pragma unroll
            for (int t = 0; t < 4; t++) {
                uint32_t b4[4];
                ldm_x4(b4, Kb + (t * 16) * QSTR + kb + b_off);
                mma_f16(s[2 * t],     aH, b4[0], b4[1]);
                mma_f16(s[2 * t],     aL, b4[0], b4[1]);
                mma_f16(s[2 * t + 1], aH, b4[2], b4[3]);
                mma_f16(s[2 * t + 1], aL, b4[2], b4[3]);
            }
        }

        // ---- logit scale ----
#pragma unroll
        for (int ni = 0; ni < 8; ni++)
#pragma unroll
            for (int j = 0; j < 4; j++) s[ni][j] *= lscale;

        // ---- causal mask ----
        const int row0 = qt * 128 + wr + g;
        if (causal && (kt * 64 + 63 > qt * 128 + wr)) {
            const int col0 = kt * 64 + 2 * cq;
#pragma unroll
            for (int ni = 0; ni < 8; ni++)
#pragma unroll
                for (int j = 0; j < 4; j++) {
                    int row = row0 + (j >> 1) * 8;
                    int col = col0 + ni * 8 + (j & 1);
                    if (col > row) s[ni][j] = -1e30f;
                }
        }

        // ---- online softmax ----
#pragma unroll
        for (int h = 0; h < 2; h++) {
            float rm = -1e30f;
#pragma unroll
            for (int ni = 0; ni < 8; ni++)
                rm = fmaxf(rm, fmaxf(s[ni][2 * h], s[ni][2 * h + 1]));
            rm = fmaxf(rm, __shfl_xor_sync(0xffffffffu, rm, 1));
            rm = fmaxf(rm, __shfl_xor_sync(0xffffffffu, rm, 2));
            const float mn = fmaxf(m_i[h], rm);
            const float alpha = __expf(m_i[h] - mn);
            m_i[h] = mn;
            float rs = 0.f;
#pragma unroll
            for (int ni = 0; ni < 8; ni++) {
                float e0 = __expf(s[ni][2 * h]     - mn);
                float e1 = __expf(s[ni][2 * h + 1] - mn);
                s[ni][2 * h] = e0; s[ni][2 * h + 1] = e1;
                rs += e0 + e1;
            }
            rs += __shfl_xor_sync(0xffffffffu, rs, 1);
            rs += __shfl_xor_sync(0xffffffffu, rs, 2);
            l_i[h] = l_i[h] * alpha + rs;
#pragma unroll
            for (int np = 0; np < 16; np++) {
                o[np][2 * h]     *= alpha;
                o[np][2 * h + 1] *= alpha;
            }
        }

        // ---- O += P V (fp16, P split 2-term) ----
#pragma unroll
        for (int ks = 0; ks < 4; ks++) {
            uint32_t aPh[4], aPl[4];
#pragma unroll
            for (int q = 0; q < 4; q++) {
                const int ni = 2 * ks + (q >> 1);
                const int j0 = (q & 1) * 2;
                float e0 = s[ni][j0], e1 = s[ni][j0 + 1];
                __half2 hh = __floats2half2_rn(e0, e1);
                aPh[q] = *(uint32_t*)&hh;
                float2 hf = __half22float2(hh);
                __half2 ll = __floats2half2_rn(e0 - hf.x, e1 - hf.y);
                aPl[q] = *(uint32_t*)&ll;
            }
#pragma unroll
            for (int np = 0; np < 8; np++) {
                uint32_t bv[4];
                ldm_x4_t(bv, Vb + (ks * 16) * QSTR + np * 32 + a_off);
                mma_f16(o[2 * np],     aPh, bv[0], bv[1]);
                mma_f16(o[2 * np],     aPl, bv[0], bv[1]);
                mma_f16(o[2 * np + 1], aPh, bv[2], bv[3]);
                mma_f16(o[2 * np + 1], aPl, bv[2], bv[3]);
            }
        }
        __syncthreads();
    }

    // ---- epilogue: normalize, split to fp16 hi/lo ----
    const float inv0 = 1.f / l_i[0];
    const float inv1 = 1.f / l_i[1];
    const size_t rowa = (size_t)(b * N_ + qt * 128 + wr + g);
    const int colb = hq * D_ + 2 * cq;
#pragma unroll
    for (int np = 0; np < 16; np++) {
        const size_t off0 = rowa * E_ + colb + np * 8;
        split_store2h(ah, al, off0, o[np][0] * inv0, o[np][1] * inv0);
        const size_t off1 = (rowa + 8) * E_ + colb + np * 8;
        split_store2h(ah, al, off1, o[np][2] * inv1, o[np][3] * inv1);
    }
}

// =================================================================
extern "C" void kernel_launch(void* const* d_in, const int* in_sizes, int n_in,
                              void* d_out, int out_size)
{
    const float* query = (const float*)d_in[0];
    const float* key   = (const float*)d_in[1];
    const float* value = (const float*)d_in[2];
    const float* Wq = (const float*)d_in[3];
    const float* bq = (const float*)d_in[4];
    const float* Wk = (const float*)d_in[5];
    const float* bk = (const float*)d_in[6];
    const float* Wv = (const float*)d_in[7];
    const float* bv = (const float*)d_in[8];
    const float* Wo = (const float*)d_in[9];
    const float* bo = (const float*)d_in[10];
    const int* is_causal = (const int*)d_in[11];
    float* out = (float*)d_out;

    __half *sqh, *sql, *skh, *skl, *svh, *svl;
    __half *wq, *wk, *wv, *wo;
    __half *qhp, *qlp, *kfp, *vfp, *ahp, *alp;
    cudaGetSymbolAddress((void**)&sqh, s_q_hi);  cudaGetSymbolAddress((void**)&sql, s_q_lo);
    cudaGetSymbolAddress((void**)&skh, s_k_hi);  cudaGetSymbolAddress((void**)&skl, s_k_lo);
    cudaGetSymbolAddress((void**)&svh, s_v_hi);  cudaGetSymbolAddress((void**)&svl, s_v_lo);
    cudaGetSymbolAddress((void**)&wq, w_q);      cudaGetSymbolAddress((void**)&wk, w_k);
    cudaGetSymbolAddress((void**)&wv, w_v);      cudaGetSymbolAddress((void**)&wo, w_o);
    cudaGetSymbolAddress((void**)&qhp, q_h16);   cudaGetSymbolAddress((void**)&qlp, q_l16);
    cudaGetSymbolAddress((void**)&kfp, k_f16);   cudaGetSymbolAddress((void**)&vfp, v_f16);
    cudaGetSymbolAddress((void**)&ahp, a_h16);   cudaGetSymbolAddress((void**)&alp, a_l16);

    // ---- fused converts (7 segments, one launch) ----
    const int actN4 = (MR_ * E_) / 4;
    const int wqN4  = (E_ * E_) / 4;
    const int wkN4  = (KVE_ * E_) / 4;
    SplitSegs segs;
    segs.x[0] = query; segs.hi[0] = sqh; segs.lo[0] = sql;
    segs.x[1] = key;   segs.hi[1] = skh; segs.lo[1] = skl;
    segs.x[2] = value; segs.hi[2] = svh; segs.lo[2] = svl;
    segs.x[3] = Wq;    segs.hi[3] = wq;  segs.lo[3] = nullptr;
    segs.x[4] = Wk;    segs.hi[4] = wk;  segs.lo[4] = nullptr;
    segs.x[5] = Wv;    segs.hi[5] = wv;  segs.lo[5] = nullptr;
    segs.x[6] = Wo;    segs.hi[6] = wo;  segs.lo[6] = nullptr;
    int nb = 0;
    const int segBlocks[7] = { actN4/256, actN4/256, actN4/256,
                               wqN4/256, wkN4/256, wkN4/256, wqN4/256 };
    for (int s = 0; s < 7; s++) { nb += segBlocks[s]; segs.blk_end[s] = nb; }
    split_fused<<<nb, 256>>>(segs);

    // ---- fused Q/K/V projection GEMMs ----
    cudaFuncSetAttribute(gemm_qkv, cudaFuncAttributeMaxDynamicSharedMemorySize, GSMEM);
    cudaFuncSetAttribute(gemm_o,   cudaFuncAttributeMaxDynamicSharedMemorySize, GSMEM);
    const int qkvBlocks = (E_ / BN) * (MR_ / BM) + 2 * (KVE_ / BN) * (MR_ / BM); // 768
    gemm_qkv<<<qkvBlocks, 256, GSMEM>>>(
        sqh, sql, wq, bq, qhp, qlp,
        skh, skl, wk, bk, kfp,
        svh, svl, wv, bv, vfp);

    // ---- HMMA flash attention ----
    cudaFuncSetAttribute(attn_mma, cudaFuncAttributeMaxDynamicSharedMemorySize, AT_SMEM);
    attn_mma<<<dim3(N_ / 128, B_ * HQ_), 256, AT_SMEM>>>(
        qhp, qlp, kfp, vfp, ahp, alp, is_causal);

    // ---- O projection (fp32 out) ----
    gemm_o<<<dim3(E_ / BN, MR_ / BM), 256, GSMEM>>>(ahp, alp, wo, bo, out);
}

// round 8
// speedup vs baseline: 5.1442x; 1.1179x over previous
#include <cuda_runtime.h>
#include <cuda_bf16.h>
#include <cuda_fp16.h>
#include <cstdint>
#include <math.h>

#define E_    2048
#define HQ_   16
#define HK_   4
#define D_    128
#define KVE_  512
#define B_    2
#define N_    2048
#define MR_   (B_ * N_)   // 4096 rows

// ---------------- scratch (no allocations allowed) ----------------
__device__ __half s_q_hi[(size_t)MR_ * E_],  s_q_lo[(size_t)MR_ * E_];
__device__ __half s_k_hi[(size_t)MR_ * E_],  s_k_lo[(size_t)MR_ * E_];
__device__ __half s_v_hi[(size_t)MR_ * E_],  s_v_lo[(size_t)MR_ * E_];
__device__ __half w_q[(size_t)E_ * E_];
__device__ __half w_k[(size_t)KVE_ * E_];
__device__ __half w_v[(size_t)KVE_ * E_];
__device__ __half w_o[(size_t)E_ * E_];
__device__ __half q_h16[(size_t)MR_ * E_], q_l16[(size_t)MR_ * E_];
__device__ __half k_f16[(size_t)MR_ * KVE_];
__device__ __half v_f16[(size_t)MR_ * KVE_];
__device__ __half a_h16[(size_t)MR_ * E_], a_l16[(size_t)MR_ * E_];

// ================= helpers =================
__device__ __forceinline__ uint32_t smem_u32(const void* p) {
    uint32_t a;
    asm("{ .reg .u64 t; cvta.to.shared.u64 t, %1; cvt.u32.u64 %0, t; }" : "=r"(a) : "l"(p));
    return a;
}
__device__ __forceinline__ void cp16(uint32_t saddr, const void* g) {
    asm volatile("cp.async.cg.shared.global [%0], [%1], 16;" :: "r"(saddr), "l"(g));
}
#define CP_COMMIT() asm volatile("cp.async.commit_group;" ::: "memory")
#define CP_WAIT(n)  asm volatile("cp.async.wait_group %0;" :: "n"(n) : "memory")

__device__ __forceinline__ void ldm_x4(uint32_t* r, uint32_t addr) {
    asm volatile("ldmatrix.sync.aligned.m8n8.x4.shared.b16 {%0,%1,%2,%3}, [%4];"
                 : "=r"(r[0]), "=r"(r[1]), "=r"(r[2]), "=r"(r[3]) : "r"(addr));
}
__device__ __forceinline__ void ldm_x4_t(uint32_t* r, uint32_t addr) {
    asm volatile("ldmatrix.sync.aligned.m8n8.x4.trans.shared.b16 {%0,%1,%2,%3}, [%4];"
                 : "=r"(r[0]), "=r"(r[1]), "=r"(r[2]), "=r"(r[3]) : "r"(addr));
}
__device__ __forceinline__ void mma_f16(float* d, const uint32_t* a,
                                        uint32_t b0, uint32_t b1) {
    asm volatile(
        "mma.sync.aligned.m16n8k16.row.col.f32.f16.f16.f32 "
        "{%0,%1,%2,%3}, {%4,%5,%6,%7}, {%8,%9}, {%0,%1,%2,%3};"
        : "+f"(d[0]), "+f"(d[1]), "+f"(d[2]), "+f"(d[3])
        : "r"(a[0]), "r"(a[1]), "r"(a[2]), "r"(a[3]), "r"(b0), "r"(b1));
}
__device__ __forceinline__ void split_store2h(__half* hi, __half* lo,
                                              size_t off, float y0, float y1) {
    __half h0 = __float2half(y0);
    __half h1 = __float2half(y1);
    __half l0 = __float2half(y0 - __half2float(h0));
    __half l1 = __float2half(y1 - __half2float(h1));
    *(__half2*)(hi + off) = __halves2half2(h0, h1);
    *(__half2*)(lo + off) = __halves2half2(l0, l1);
}

// ========== fused convert: fp32 -> fp16 hi(/lo) over 7 segments ==========
struct SplitSegs {
    const float* x[7];
    __half* hi[7];
    __half* lo[7];
    int blk_end[7];
};

__global__ void split_fused(SplitSegs segs)
{
    int bid = blockIdx.x;
    int seg = 0;
    int base = 0;
#pragma unroll
    for (int s = 0; s < 7; s++) {
        if (bid >= segs.blk_end[s]) { seg = s + 1; base = segs.blk_end[s]; }
    }
    int i = (bid - base) * 256 + threadIdx.x;
    float4 v = ((const float4*)segs.x[seg])[i];
    __half h0 = __float2half(v.x);
    __half h1 = __float2half(v.y);
    __half h2 = __float2half(v.z);
    __half h3 = __float2half(v.w);
    __half* hi = segs.hi[seg];
    ((__half2*)hi)[i * 2]     = __halves2half2(h0, h1);
    ((__half2*)hi)[i * 2 + 1] = __halves2half2(h2, h3);
    __half* lo = segs.lo[seg];
    if (lo) {
        __half l0 = __float2half(v.x - __half2float(h0));
        __half l1 = __float2half(v.y - __half2float(h1));
        __half l2 = __float2half(v.z - __half2float(h2));
        __half l3 = __float2half(v.w - __half2float(h3));
        ((__half2*)lo)[i * 2]     = __halves2half2(l0, l1);
        ((__half2*)lo)[i * 2 + 1] = __halves2half2(l2, l3);
    }
}

// ================= HMMA NT GEMM core (fp16, A-split 2-term, 3-stage) =================
#define BM 128
#define BN 128
#define BK 32
#define LDSB 80
#define TILE_B (128 * LDSB)      // 10240
#define STAGE_B (3 * TILE_B)     // Ah, Al, B  = 30720
#define GSMEM (3 * STAGE_B)      // 92160 (3 stages)

__device__ __forceinline__ void load_chunk(uint32_t sb, int stage,
    const __half* __restrict__ Ah, const __half* __restrict__ Al,
    const __half* __restrict__ Bw, int K, int tid)
{
    const __half* srcs[3] = { Ah, Al, Bw };
    uint32_t base = sb + stage * STAGE_B;
#pragma unroll
    for (int t = 0; t < 3; t++) {
#pragma unroll
        for (int it = 0; it < 2; it++) {
            int idx = tid + it * 256;
            int r = idx >> 2;
            int c = idx & 3;
            cp16(base + t * TILE_B + r * LDSB + c * 16,
                 srcs[t] + (size_t)r * K + c * 8);
        }
    }
}

__device__ __forceinline__ void gemm_mainloop(
    uint32_t sb, const __half* pAh, const __half* pAl, const __half* pB,
    int K, int tid, int lane, int wm, int wn, float acc[4][4][4])
{
    const uint32_t a_off = (uint32_t)((lane & 15) * LDSB + (lane >> 4) * 16);
    const uint32_t b_off = (uint32_t)(((lane & 7) + (lane >> 4) * 8) * LDSB
                                      + ((lane >> 3) & 1) * 16);
    const int nch = K >> 5;    // >= 2 always (K = 2048)

    load_chunk(sb, 0, pAh, pAl, pB, K, tid);
    CP_COMMIT();
    load_chunk(sb, 1, pAh + BK, pAl + BK, pB + BK, K, tid);
    CP_COMMIT();

    int cst = 0;   // compute stage
    int lst = 2;   // next load stage
    for (int c = 0; c < nch; c++) {
        if (c + 1 < nch) { CP_WAIT(1); } else { CP_WAIT(0); }
        __syncthreads();

        const uint32_t stb = sb + cst * STAGE_B;
        const uint32_t Ah_b = stb + 0 * TILE_B;
        const uint32_t Al_b = stb + 1 * TILE_B;
        const uint32_t Bw_b = stb + 2 * TILE_B;

#pragma unroll
        for (int ks = 0; ks < 2; ks++) {
            const uint32_t kbyte = ks * 32;
            uint32_t aH[4][4], bW[2][4];
#pragma unroll
            for (int mi = 0; mi < 4; mi++)
                ldm_x4(aH[mi], Ah_b + (wm * 64 + mi * 16) * LDSB + kbyte + a_off);
#pragma unroll
            for (int nb = 0; nb < 2; nb++)
                ldm_x4(bW[nb], Bw_b + (wn * 32 + nb * 16) * LDSB + kbyte + b_off);
#pragma unroll
            for (int mi = 0; mi < 4; mi++)
#pragma unroll
                for (int ni = 0; ni < 4; ni++)
                    mma_f16(acc[mi][ni], aH[mi], bW[ni >> 1][(ni & 1) * 2],
                                                  bW[ni >> 1][(ni & 1) * 2 + 1]);
            uint32_t aL[4][4];
#pragma unroll
            for (int mi = 0; mi < 4; mi++)
                ldm_x4(aL[mi], Al_b + (wm * 64 + mi * 16) * LDSB + kbyte + a_off);
#pragma unroll
            for (int mi = 0; mi < 4; mi++)
#pragma unroll
                for (int ni = 0; ni < 4; ni++)
                    mma_f16(acc[mi][ni], aL[mi], bW[ni >> 1][(ni & 1) * 2],
                                                  bW[ni >> 1][(ni & 1) * 2 + 1]);
        }

        if (c + 2 < nch) {
            const size_t kb = (size_t)(c + 2) * BK;
            load_chunk(sb, lst, pAh + kb, pAl + kb, pB + kb, K, tid);
            CP_COMMIT();
        }
        cst = (cst == 2) ? 0 : cst + 1;
        lst = (lst == 2) ? 0 : lst + 1;
    }
}

// ---- fused Q/K/V projection GEMM (one launch) ----
__global__ void __launch_bounds__(256, 2) gemm_qkv(
    const __half* __restrict__ sqh, const __half* __restrict__ sql,
    const __half* __restrict__ wq, const float* __restrict__ bq,
    __half* __restrict__ qhp, __half* __restrict__ qlp,
    const __half* __restrict__ skh, const __half* __restrict__ skl,
    const __half* __restrict__ wk, const float* __restrict__ bk,
    __half* __restrict__ kfp,
    const __half* __restrict__ svh, const __half* __restrict__ svl,
    const __half* __restrict__ wv, const float* __restrict__ bv,
    __half* __restrict__ vfp)
{
    extern __shared__ char smem[];
    const uint32_t sb = smem_u32(smem);
    const int tid = threadIdx.x;
    const int lane = tid & 31;
    const int wid = tid >> 5;
    const int wm = wid & 1;
    const int wn = wid >> 1;

    const int bid = blockIdx.x;
    const int seg = (bid < 512) ? 0 : (bid < 640 ? 1 : 2);
    const int local = bid - (seg == 0 ? 0 : (seg == 1 ? 512 : 640));
    const int tilesX = (seg == 0) ? (E_ / BN) : (KVE_ / BN);
    const int m0 = (local / tilesX) * BM;
    const int n0 = (local % tilesX) * BN;

    const __half* Ah = (seg == 0) ? sqh : (seg == 1 ? skh : svh);
    const __half* Al = (seg == 0) ? sql : (seg == 1 ? skl : svl);
    const __half* Bw = (seg == 0) ? wq : (seg == 1 ? wk : wv);
    const float* bias = (seg == 0) ? bq : (seg == 1 ? bk : bv);
    const int Nn = (seg == 0) ? E_ : KVE_;

    float acc[4][4][4];
#pragma unroll
    for (int i = 0; i < 4; i++)
#pragma unroll
        for (int j = 0; j < 4; j++)
#pragma unroll
            for (int q = 0; q < 4; q++) acc[i][j][q] = 0.f;

    gemm_mainloop(sb, Ah + (size_t)m0 * E_, Al + (size_t)m0 * E_,
                  Bw + (size_t)n0 * E_, E_, tid, lane, wm, wn, acc);

    const int g = lane >> 2;
    const int cq = lane & 3;
#pragma unroll
    for (int mi = 0; mi < 4; mi++) {
#pragma unroll
        for (int ni = 0; ni < 4; ni++) {
            const int col = n0 + wn * 32 + ni * 8 + cq * 2;
            const float b0 = bias[col];
            const float b1 = bias[col + 1];
#pragma unroll
            for (int h = 0; h < 2; h++) {
                const int row = m0 + wm * 64 + mi * 16 + g + h * 8;
                const float y0 = acc[mi][ni][h * 2 + 0] + b0;
                const float y1 = acc[mi][ni][h * 2 + 1] + b1;
                const size_t off = (size_t)row * Nn + col;
                if (seg == 0)      split_store2h(qhp, qlp, off, y0, y1);
                else if (seg == 1) *(__half2*)(kfp + off) = __floats2half2_rn(y0, y1);
                else               *(__half2*)(vfp + off) = __floats2half2_rn(y0, y1);
            }
        }
    }
}

// ---- O projection GEMM (fp32 out) ----
__global__ void __launch_bounds__(256, 2) gemm_o(
    const __half* __restrict__ Ahi, const __half* __restrict__ Alo,
    const __half* __restrict__ Bw,
    const float* __restrict__ bias, float* __restrict__ C)
{
    extern __shared__ char smem[];
    const uint32_t sb = smem_u32(smem);
    const int tid = threadIdx.x;
    const int lane = tid & 31;
    const int wid = tid >> 5;
    const int wm = wid & 1;
    const int wn = wid >> 1;
    const int m0 = blockIdx.y * BM;
    const int n0 = blockIdx.x * BN;

    float acc[4][4][4];
#pragma unroll
    for (int i = 0; i < 4; i++)
#pragma unroll
        for (int j = 0; j < 4; j++)
#pragma unroll
            for (int q = 0; q < 4; q++) acc[i][j][q] = 0.f;

    gemm_mainloop(sb, Ahi + (size_t)m0 * E_, Alo + (size_t)m0 * E_,
                  Bw + (size_t)n0 * E_, E_, tid, lane, wm, wn, acc);

    const int g = lane >> 2;
    const int cq = lane & 3;
#pragma unroll
    for (int mi = 0; mi < 4; mi++) {
#pragma unroll
        for (int ni = 0; ni < 4; ni++) {
            const int col = n0 + wn * 32 + ni * 8 + cq * 2;
            const float b0 = bias[col];
            const float b1 = bias[col + 1];
#pragma unroll
            for (int h = 0; h < 2; h++) {
                const int row = m0 + wm * 64 + mi * 16 + g + h * 8;
                float2 v;
                v.x = acc[mi][ni][h * 2 + 0] + b0;
                v.y = acc[mi][ni][h * 2 + 1] + b1;
                *(float2*)(C + (size_t)row * E_ + col) = v;
            }
        }
    }
}

// =================================================================
// HMMA flash attention: Q split fp16 2-term, K/V single fp16, 3-stage KV.
// =================================================================
#define QSTR 272
#define AT_QH   0
#define AT_QL   (128 * QSTR)
#define AT_KV0  (2 * 128 * QSTR)       // 69632
#define AT_STG  (2 * 64 * QSTR)        // 34816 (K, V)
#define AT_K    0
#define AT_V    (64 * QSTR)
#define AT_SMEM (AT_KV0 + 3 * AT_STG)  // 174080

__device__ __forceinline__ void attn_load_kv(uint32_t sb, int stage, int b, int hk,
                                             int kt, const __half* kf,
                                             const __half* vf, int tid)
{
    const uint32_t base = sb + AT_KV0 + stage * AT_STG;
    const size_t rowg = (size_t)(b * N_ + kt * 64);
#pragma unroll
    for (int it = 0; it < 8; it++) {
        int idx = tid + it * 256;
        int buf = idx >> 10;
        int r = (idx & 1023) >> 4;
        int c = idx & 15;
        uint32_t dst = base + (buf ? AT_V : AT_K) + r * QSTR + c * 16;
        const __half* src = buf ? vf : kf;
        cp16(dst, src + (rowg + r) * KVE_ + hk * D_ + c * 8);
    }
}

__global__ void __launch_bounds__(256, 1) attn_mma(
    const __half* __restrict__ qh, const __half* __restrict__ ql,
    const __half* __restrict__ kf, const __half* __restrict__ vf,
    __half* __restrict__ ah, __half* __restrict__ al,
    const int* __restrict__ causal_p)
{
    extern __shared__ char smem[];
    const uint32_t sb = smem_u32(smem);
    const int tid = threadIdx.x;
    const int lane = tid & 31;
    const int wid = tid >> 5;
    const int qt = (int)(gridDim.x - 1 - blockIdx.x);  // heavy tiles first
    const int bh = blockIdx.y;
    const int b  = bh >> 4;
    const int hq = bh & 15;
    const int hk = hq >> 2;
    const int wr = wid * 16;
    const int g = lane >> 2;
    const int cq = lane & 3;
    const bool causal = (causal_p[0] != 0);
    const float lscale = 0.08838834764831845f;  // 1/sqrt(128)

    const uint32_t a_off = (uint32_t)((lane & 15) * QSTR + (lane >> 4) * 16);
    const uint32_t b_off = (uint32_t)(((lane & 7) + (lane >> 4) * 8) * QSTR
                                      + ((lane >> 3) & 1) * 16);

    const int ktend = causal ? 2 * (qt + 1) : (N_ / 64);

    // ---- prologue: Q tile + kv(0) in group 0, kv(1) in group 1 ----
    {
        const size_t rowg = (size_t)(b * N_ + qt * 128);
#pragma unroll
        for (int it = 0; it < 16; it++) {
            int idx = tid + it * 256;
            int buf = idx >> 11;
            int r = (idx & 2047) >> 4;
            int c = idx & 15;
            uint32_t dst = sb + (buf ? AT_QL : AT_QH) + r * QSTR + c * 16;
            const __half* src = buf ? ql : qh;
            cp16(dst, src + (rowg + r) * E_ + hq * D_ + c * 8);
        }
    }
    attn_load_kv(sb, 0, b, hk, 0, kf, vf, tid);
    CP_COMMIT();
    if (1 < ktend) {
        attn_load_kv(sb, 1, b, hk, 1, kf, vf, tid);
        CP_COMMIT();
    }

    float m_i[2] = { -1e30f, -1e30f };
    float l_i[2] = { 0.f, 0.f };
    float o[16][4];
#pragma unroll
    for (int i = 0; i < 16; i++)
#pragma unroll
        for (int j = 0; j < 4; j++) o[i][j] = 0.f;

    int cst = 0;   // compute stage
    int lst = 2;   // next load stage
    for (int kt = 0; kt < ktend; kt++) {
        if (kt + 1 < ktend) { CP_WAIT(1); } else { CP_WAIT(0); }
        __syncthreads();

        const uint32_t Kb = sb + AT_KV0 + cst * AT_STG + AT_K;
        const uint32_t Vb = sb + AT_KV0 + cst * AT_STG + AT_V;

        // ---- S = Q K^T (16 rows x 64 cols per warp), fp16 2-term ----
        float s[8][4];
#pragma unroll
        for (int i = 0; i < 8; i++)
#pragma unroll
            for (int j = 0; j < 4; j++) s[i][j] = 0.f;

#pragma unroll
        for (int ks = 0; ks < 8; ks++) {
            const uint32_t kb = ks * 32;
            uint32_t aH[4], aL[4];
            ldm_x4(aH, sb + AT_QH + wr * QSTR + kb + a_off);
            ldm_x4(aL, sb + AT_QL + wr * QSTR + kb + a_off);
#pragma unroll
            for (int t = 0; t < 4; t++) {
                uint32_t b4[4];
                ldm_x4(b4, Kb + (t * 16) * QSTR + kb + b_off);
                mma_f16(s[2 * t],     aH, b4[0], b4[1]);
                mma_f16(s[2 * t],     aL, b4[0], b4[1]);
                mma_f16(s[2 * t + 1], aH, b4[2], b4[3]);
                mma_f16(s[2 * t + 1], aL, b4[2], b4[3]);
            }
        }

        // ---- logit scale ----
#pragma unroll
        for (int ni = 0; ni < 8; ni++)
#pragma unroll
            for (int j = 0; j < 4; j++) s[ni][j] *= lscale;

        // ---- causal mask ----
        const int row0 = qt * 128 + wr + g;
        if (causal && (kt * 64 + 63 > qt * 128 + wr)) {
            const int col0 = kt * 64 + 2 * cq;
#pragma unroll
            for (int ni = 0; ni < 8; ni++)
#pragma unroll
                for (int j = 0; j < 4; j++) {
                    int row = row0 + (j >> 1) * 8;
                    int col = col0 + ni * 8 + (j & 1);
                    if (col > row) s[ni][j] = -1e30f;
                }
        }

        // ---- online softmax ----
#pragma unroll
        for (int h = 0; h < 2; h++) {
            float rm = -1e30f;
#pragma unroll
            for (int ni = 0; ni < 8; ni++)
                rm = fmaxf(rm, fmaxf(s[ni][2 * h], s[ni][2 * h + 1]));
            rm = fmaxf(rm, __shfl_xor_sync(0xffffffffu, rm, 1));
            rm = fmaxf(rm, __shfl_xor_sync(0xffffffffu, rm, 2));
            const float mn = fmaxf(m_i[h], rm);
            const float alpha = __expf(m_i[h] - mn);
            m_i[h] = mn;
            float rs = 0.f;
#pragma unroll
            for (int ni = 0; ni < 8; ni++) {
                float e0 = __expf(s[ni][2 * h]     - mn);
                float e1 = __expf(s[ni][2 * h + 1] - mn);
                s[ni][2 * h] = e0; s[ni][2 * h + 1] = e1;
                rs += e0 + e1;
            }
            rs += __shfl_xor_sync(0xffffffffu, rs, 1);
            rs += __shfl_xor_sync(0xffffffffu, rs, 2);
            l_i[h] = l_i[h] * alpha + rs;
#pragma unroll
            for (int np = 0; np < 16; np++) {
                o[np][2 * h]     *= alpha;
                o[np][2 * h + 1] *= alpha;
            }
        }

        // ---- O += P V (fp16, P split 2-term) ----
#pragma unroll
        for (int ks = 0; ks < 4; ks++) {
            uint32_t aPh[4], aPl[4];
#pragma unroll
            for (int q = 0; q < 4; q++) {
                const int ni = 2 * ks + (q >> 1);
                const int j0 = (q & 1) * 2;
                float e0 = s[ni][j0], e1 = s[ni][j0 + 1];
                __half2 hh = __floats2half2_rn(e0, e1);
                aPh[q] = *(uint32_t*)&hh;
                float2 hf = __half22float2(hh);
                __half2 ll = __floats2half2_rn(e0 - hf.x, e1 - hf.y);
                aPl[q] = *(uint32_t*)&ll;
            }
#pragma unroll
            for (int np = 0; np < 8; np++) {
                uint32_t bv[4];
                ldm_x4_t(bv, Vb + (ks * 16) * QSTR + np * 32 + a_off);
                mma_f16(o[2 * np],     aPh, bv[0], bv[1]);
                mma_f16(o[2 * np],     aPl, bv[0], bv[1]);
                mma_f16(o[2 * np + 1], aPh, bv[2], bv[3]);
                mma_f16(o[2 * np + 1], aPl, bv[2], bv[3]);
            }
        }

        if (kt + 2 < ktend) {
            attn_load_kv(sb, lst, b, hk, kt + 2, kf, vf, tid);
            CP_COMMIT();
        }
        cst = (cst == 2) ? 0 : cst + 1;
        lst = (lst == 2) ? 0 : lst + 1;
    }

    // ---- epilogue: normalize, split to fp16 hi/lo ----
    const float inv0 = 1.f / l_i[0];
    const float inv1 = 1.f / l_i[1];
    const size_t rowa = (size_t)(b * N_ + qt * 128 + wr + g);
    const int colb = hq * D_ + 2 * cq;
#pragma unroll
    for (int np = 0; np < 16; np++) {
        const size_t off0 = rowa * E_ + colb + np * 8;
        split_store2h(ah, al, off0, o[np][0] * inv0, o[np][1] * inv0);
        const size_t off1 = (rowa + 8) * E_ + colb + np * 8;
        split_store2h(ah, al, off1, o[np][2] * inv1, o[np][3] * inv1);
    }
}

// =================================================================
extern "C" void kernel_launch(void* const* d_in, const int* in_sizes, int n_in,
                              void* d_out, int out_size)
{
    const float* query = (const float*)d_in[0];
    const float* key   = (const float*)d_in[1];
    const float* value = (const float*)d_in[2];
    const float* Wq = (const float*)d_in[3];
    const float* bq = (const float*)d_in[4];
    const float* Wk = (const float*)d_in[5];
    const float* bk = (const float*)d_in[6];
    const float* Wv = (const float*)d_in[7];
    const float* bv = (const float*)d_in[8];
    const float* Wo = (const float*)d_in[9];
    const float* bo = (const float*)d_in[10];
    const int* is_causal = (const int*)d_in[11];
    float* out = (float*)d_out;

    __half *sqh, *sql, *skh, *skl, *svh, *svl;
    __half *wq, *wk, *wv, *wo;
    __half *qhp, *qlp, *kfp, *vfp, *ahp, *alp;
    cudaGetSymbolAddress((void**)&sqh, s_q_hi);  cudaGetSymbolAddress((void**)&sql, s_q_lo);
    cudaGetSymbolAddress((void**)&skh, s_k_hi);  cudaGetSymbolAddress((void**)&skl, s_k_lo);
    cudaGetSymbolAddress((void**)&svh, s_v_hi);  cudaGetSymbolAddress((void**)&svl, s_v_lo);
    cudaGetSymbolAddress((void**)&wq, w_q);      cudaGetSymbolAddress((void**)&wk, w_k);
    cudaGetSymbolAddress((void**)&wv, w_v);      cudaGetSymbolAddress((void**)&wo, w_o);
    cudaGetSymbolAddress((void**)&qhp, q_h16);   cudaGetSymbolAddress((void**)&qlp, q_l16);
    cudaGetSymbolAddress((void**)&kfp, k_f16);   cudaGetSymbolAddress((void**)&vfp, v_f16);
    cudaGetSymbolAddress((void**)&ahp, a_h16);   cudaGetSymbolAddress((void**)&alp, a_l16);

    // ---- fused converts (7 segments, one launch) ----
    const int actN4 = (MR_ * E_) / 4;
    const int wqN4  = (E_ * E_) / 4;
    const int wkN4  = (KVE_ * E_) / 4;
    SplitSegs segs;
    segs.x[0] = query; segs.hi[0] = sqh; segs.lo[0] = sql;
    segs.x[1] = key;   segs.hi[1] = skh; segs.lo[1] = skl;
    segs.x[2] = value; segs.hi[2] = svh; segs.lo[2] = svl;
    segs.x[3] = Wq;    segs.hi[3] = wq;  segs.lo[3] = nullptr;
    segs.x[4] = Wk;    segs.hi[4] = wk;  segs.lo[4] = nullptr;
    segs.x[5] = Wv;    segs.hi[5] = wv;  segs.lo[5] = nullptr;
    segs.x[6] = Wo;    segs.hi[6] = wo;  segs.lo[6] = nullptr;
    int nb = 0;
    const int segBlocks[7] = { actN4/256, actN4/256, actN4/256,
                               wqN4/256, wkN4/256, wkN4/256, wqN4/256 };
    for (int s = 0; s < 7; s++) { nb += segBlocks[s]; segs.blk_end[s] = nb; }
    split_fused<<<nb, 256>>>(segs);

    // ---- fused Q/K/V projection GEMMs ----
    cudaFuncSetAttribute(gemm_qkv, cudaFuncAttributeMaxDynamicSharedMemorySize, GSMEM);
    cudaFuncSetAttribute(gemm_o,   cudaFuncAttributeMaxDynamicSharedMemorySize, GSMEM);
    const int qkvBlocks = (E_ / BN) * (MR_ / BM) + 2 * (KVE_ / BN) * (MR_ / BM); // 768
    gemm_qkv<<<qkvBlocks, 256, GSMEM>>>(
        sqh, sql, wq, bq, qhp, qlp,
        skh, skl, wk, bk, kfp,
        svh, svl, wv, bv, vfp);

    // ---- HMMA flash attention ----
    cudaFuncSetAttribute(attn_mma, cudaFuncAttributeMaxDynamicSharedMemorySize, AT_SMEM);
    attn_mma<<<dim3(N_ / 128, B_ * HQ_), 256, AT_SMEM>>>(
        qhp, qlp, kfp, vfp, ahp, alp, is_causal);

    // ---- O projection (fp32 out) ----
    gemm_o<<<dim3(E_ / BN, MR_ / BM), 256, GSMEM>>>(ahp, alp, wo, bo, out);
}